// round 10
// baseline (speedup 1.0000x reference)
#include <cuda_runtime.h>
#include <math.h>

#define BATCH 65536
#define FULL 0xffffffffu

typedef unsigned long long u64;

// -------- device scratch (allocation-free rule: __device__ globals) --------
__device__ float g_f [(size_t)BATCH * 420];   // DyConv output
__device__ float g_hh[(size_t)BATCH * 256];   // relu(f@W1+b1)

// -------- constant weight image (packed layouts), staged via g_wbuf --------
#define OFF_WE   0       // 336 float2: [(ci*3+tp)*8+op], op<7 valid
#define OFF_BE   672     // 14
#define OFF_WQ   688     // 112 [d*8+h]
#define OFF_WK   800     // 112
#define OFF_WV   912     // 112
#define OFF_BQ   1024    // 8
#define OFF_BKC  1032    // 8
#define OFF_BV   1040    // 8
#define OFF_WO   1048    // 64 float2: [h*8+dp], dp<7 valid
#define OFF_BO   1176    // 14
#define OFF_F1   1192    // 400 float2: [f*8+dp] = (F1[2dp][f], F1[2dp+1][f])
#define OFF_F2   1992    // 400 float2: [f*8+dp] = (F2[f][2dp], F2[f][2dp+1])
#define OFF_G    2792    // 14
#define OFF_B    2808    // 14
#define OFF_ADJ  2824    // 112 float2: [i*8+jp], jp<7 valid
#define CW_TOTAL 3048

__device__   __align__(16) float g_wbuf[CW_TOTAL];
__constant__ __align__(16) float cbuf[CW_TOTAL];

// ---------------- packed f32x2 ops on b64 registers ----------------
__device__ __forceinline__ u64 pack2(float x, float y) {
    u64 r; asm("mov.b64 %0, {%1, %2};" : "=l"(r) : "f"(x), "f"(y)); return r;
}
__device__ __forceinline__ u64 dup2(float s) { return pack2(s, s); }
__device__ __forceinline__ void unpack2(u64 v, float& x, float& y) {
    asm("mov.b64 {%0, %1}, %2;" : "=f"(x), "=f"(y) : "l"(v));
}
__device__ __forceinline__ u64 fma2u(u64 a, u64 b, u64 c) {
    u64 d; asm("fma.rn.f32x2 %0, %1, %2, %3;" : "=l"(d) : "l"(a), "l"(b), "l"(c)); return d;
}
__device__ __forceinline__ u64 add2u(u64 a, u64 b) {
    u64 d; asm("add.rn.f32x2 %0, %1, %2;" : "=l"(d) : "l"(a), "l"(b)); return d;
}
__device__ __forceinline__ ulonglong2 lds2(const u64* p) {
    return *reinterpret_cast<const ulonglong2*>(p);
}

// ---------------- tf32 helpers ----------------
__device__ __forceinline__ void split_tf32(float x, unsigned& hi, unsigned& lo) {
    asm("cvt.rna.tf32.f32 %0, %1;" : "=r"(hi) : "f"(x));
    float r = x - __uint_as_float(hi);
    asm("cvt.rna.tf32.f32 %0, %1;" : "=r"(lo) : "f"(r));
}
__device__ __forceinline__ void mma_tf32(float* c, const unsigned* a, const unsigned* b) {
    asm volatile(
        "mma.sync.aligned.m16n8k8.row.col.f32.tf32.tf32.f32 "
        "{%0,%1,%2,%3},{%4,%5,%6,%7},{%8,%9},{%0,%1,%2,%3};"
        : "+f"(c[0]), "+f"(c[1]), "+f"(c[2]), "+f"(c[3])
        : "r"(a[0]), "r"(a[1]), "r"(a[2]), "r"(a[3]), "r"(b[0]), "r"(b[1]));
}

// ---- shuffle-scan series_decomp helper (replicate-pad MA-25) ----
__device__ __forceinline__ float decomp25(float val, int lane, int hi, int loix,
                                          int lom1, float fc0, float fc29) {
    float cs = val;
    #pragma unroll
    for (int off = 1; off < 32; off <<= 1) {
        float o = __shfl_up_sync(FULL, cs, off);
        if (lane >= off) cs += o;
    }
    float cshi = __shfl_sync(FULL, cs, hi);
    float cslo = __shfl_sync(FULL, cs, loix);
    float ssum = cshi - ((lom1 >= 0) ? cslo : 0.f);
    float x0  = __shfl_sync(FULL, val, 0);
    float x29 = __shfl_sync(FULL, val, 29);
    return val - (ssum + fc0 * x0 + fc29 * x29) * (1.f / 25.f);
}

// ============================================================================
// kPrep: build the packed constant image in g_wbuf (1 block, 256 threads)
// ============================================================================
__global__ void kPrep(
    const float* __restrict__ W_emb, const float* __restrict__ b_emb,
    const float* __restrict__ Wq, const float* __restrict__ bq,
    const float* __restrict__ Wk, const float* __restrict__ bk,
    const float* __restrict__ Wv, const float* __restrict__ bv,
    const float* __restrict__ Wo, const float* __restrict__ bo,
    const float* __restrict__ Wff1, const float* __restrict__ Wff2,
    const float* __restrict__ gnorm, const float* __restrict__ bnorm,
    const float* __restrict__ channels)
{
    const int tid = threadIdx.x;
    for (int i = tid; i < 336; i += 256) {
        int ct = i >> 3, op = i & 7;
        float a = 0.f, b = 0.f;
        if (op < 7) { a = W_emb[(2*op)*42 + ct]; b = W_emb[(2*op+1)*42 + ct]; }
        g_wbuf[OFF_WE + 2*i] = a; g_wbuf[OFF_WE + 2*i + 1] = b;
    }
    if (tid < 14) {
        g_wbuf[OFF_BE + tid] = b_emb[tid];
        g_wbuf[OFF_BO + tid] = bo[tid];
        g_wbuf[OFF_G  + tid] = gnorm[tid];
        g_wbuf[OFF_B  + tid] = bnorm[tid];
    }
    for (int i = tid; i < 112; i += 256) {
        g_wbuf[OFF_WQ + i] = Wq[i];
        g_wbuf[OFF_WK + i] = Wk[i];
        g_wbuf[OFF_WV + i] = Wv[i];
    }
    if (tid < 8) {
        g_wbuf[OFF_BQ  + tid] = bq[tid];
        g_wbuf[OFF_BKC + tid] = bk[tid];
        g_wbuf[OFF_BV  + tid] = bv[tid];
    }
    for (int i = tid; i < 64; i += 256) {
        int h = i >> 3, dp = i & 7;
        float a = 0.f, b = 0.f;
        if (dp < 7) { a = Wo[h*14 + 2*dp]; b = Wo[h*14 + 2*dp + 1]; }
        g_wbuf[OFF_WO + 2*i] = a; g_wbuf[OFF_WO + 2*i + 1] = b;
    }
    for (int i = tid; i < 400; i += 256) {
        int f = i >> 3, dp = i & 7;
        float a1 = 0.f, b1v = 0.f, a2 = 0.f, b2v = 0.f;
        if (dp < 7) {
            a1 = Wff1[(2*dp)*50 + f]; b1v = Wff1[(2*dp+1)*50 + f];
            a2 = Wff2[f*14 + 2*dp];   b2v = Wff2[f*14 + 2*dp + 1];
        }
        g_wbuf[OFF_F1 + 2*i] = a1; g_wbuf[OFF_F1 + 2*i + 1] = b1v;
        g_wbuf[OFF_F2 + 2*i] = a2; g_wbuf[OFF_F2 + 2*i + 1] = b2v;
    }
    if (tid < 14) {
        const float* row = channels + tid * 14;
        float mx = -1e30f;
        #pragma unroll
        for (int j = 0; j < 14; j++) mx = fmaxf(mx, row[j]);
        float s = 0.f;
        #pragma unroll
        for (int j = 0; j < 14; j++) s += expf(row[j] - mx);
        float inv = 1.f / s;
        #pragma unroll
        for (int j = 0; j < 7; j++) {
            g_wbuf[OFF_ADJ + tid*16 + 2*j]     = expf(row[2*j]   - mx) * inv;
            g_wbuf[OFF_ADJ + tid*16 + 2*j + 1] = expf(row[2*j+1] - mx) * inv;
        }
        g_wbuf[OFF_ADJ + tid*16 + 14] = 0.f;
        g_wbuf[OFF_ADJ + tid*16 + 15] = 0.f;
    }
}

// ============================================================================
// Kernel A: register-resident per-sample pipeline; weights in __constant__.
// 1 warp = 1 sample, lane t in [0,30) holds the 14-channel row.
// ============================================================================
__global__ __launch_bounds__(256) void kA(
    const float* __restrict__ x,
    const float* __restrict__ Wdy, const float* __restrict__ bdy)
{
    __shared__ __align__(16) float sWdy[900], sbdy[32];
    __shared__ __align__(16) float scr[8][512];   // per-warp scratch

    const int tid = threadIdx.x;
    for (int i = tid; i < 900; i += 256) sWdy[i] = Wdy[i];
    if (tid < 30) sbdy[tid] = bdy[tid];
    __syncthreads();

    const int w    = tid >> 5;
    const int lane = tid & 31;
    const int t    = (lane < 30) ? lane : 0;
    const bool act = (lane < 30);
    const int smp  = blockIdx.x * 8 + w;
    u64* scrU = reinterpret_cast<u64*>(scr[w]);

    // ---- coalesced stage of x ----
    {
        const float4* xp = reinterpret_cast<const float4*>(x + (size_t)smp * 420);
        float4* sp = reinterpret_cast<float4*>(scr[w]);
        #pragma unroll
        for (int i = lane; i < 105; i += 32) sp[i] = xp[i];
    }
    __syncwarp();
    float xr[14];
    #pragma unroll
    for (int d = 0; d < 14; d++) xr[d] = scr[w][t*14 + d];
    __syncwarp();

    // ---- Conv1d embed (kernel 3, zero pad): packed output-channel pairs ----
    u64 xe2[7];
    {
        const u64* sbe2 = reinterpret_cast<const u64*>(cbuf + OFF_BE);
        #pragma unroll
        for (int op = 0; op < 7; op++) xe2[op] = sbe2[op];
        const u64* we = reinterpret_cast<const u64*>(cbuf + OFF_WE);
        #pragma unroll
        for (int ci = 0; ci < 14; ci++) {
            float up = __shfl_up_sync(FULL, xr[ci], 1);
            float dn = __shfl_down_sync(FULL, xr[ci], 1);
            float xm  = (lane > 0)  ? up : 0.f;
            float xp2 = (lane < 29) ? dn : 0.f;
            float tap[3] = { xm, xr[ci], xp2 };
            #pragma unroll
            for (int tp = 0; tp < 3; tp++) {
                u64 xv2 = dup2(tap[tp]);
                const u64* wr = we + (ci*3 + tp) * 8;
                #pragma unroll
                for (int op = 0; op < 7; op++) xe2[op] = fma2u(xv2, wr[op], xe2[op]);
            }
        }
    }
    float xes[14];
    #pragma unroll
    for (int dp = 0; dp < 7; dp++) unpack2(xe2[dp], xes[2*dp], xes[2*dp+1]);

    // ---- QKV (packed head pairs) ----
    u64 q2[4], k2[4], v2[4];
    {
        const u64* bq2 = reinterpret_cast<const u64*>(cbuf + OFF_BQ);
        const u64* bk2 = reinterpret_cast<const u64*>(cbuf + OFF_BKC);
        const u64* bv2 = reinterpret_cast<const u64*>(cbuf + OFF_BV);
        #pragma unroll
        for (int hp = 0; hp < 4; hp++) { q2[hp]=bq2[hp]; k2[hp]=bk2[hp]; v2[hp]=bv2[hp]; }
        const u64* wq2 = reinterpret_cast<const u64*>(cbuf + OFF_WQ);
        const u64* wk2 = reinterpret_cast<const u64*>(cbuf + OFF_WK);
        const u64* wv2 = reinterpret_cast<const u64*>(cbuf + OFF_WV);
        #pragma unroll
        for (int d = 0; d < 14; d++) {
            u64 xv2 = dup2(xes[d]);
            #pragma unroll
            for (int hp = 0; hp < 4; hp++) {
                q2[hp] = fma2u(xv2, wq2[d*4+hp], q2[hp]);
                k2[hp] = fma2u(xv2, wk2[d*4+hp], k2[hp]);
                v2[hp] = fma2u(xv2, wv2[d*4+hp], v2[hp]);
            }
        }
    }
    float v[8];
    #pragma unroll
    for (int hp = 0; hp < 4; hp++) unpack2(v2[hp], v[2*hp], v[2*hp+1]);

    // stage q,k: layout [t*4 + hp] (u64) -> 2x STS.128 each
    u64* qsU = scrU;          // 120 u64
    u64* ksU = scrU + 128;    // 120 u64
    if (act) {
        *reinterpret_cast<ulonglong2*>(qsU + t*4)     = make_ulonglong2(q2[0], q2[1]);
        *reinterpret_cast<ulonglong2*>(qsU + t*4 + 2) = make_ulonglong2(q2[2], q2[3]);
        *reinterpret_cast<ulonglong2*>(ksU + t*4)     = make_ulonglong2(k2[0], k2[1]);
        *reinterpret_cast<ulonglong2*>(ksU + t*4 + 2) = make_ulonglong2(k2[2], k2[3]);
    }
    __syncwarp();

    // ---- circular correlation corr[tau] = sum_{t,h} q[t][h]*k[(t-tau)%30][h] ----
    float mv;
    {
        u64 acc2[4] = {};
        #pragma unroll
        for (int tq = 0; tq < 30; tq++) {
            int src = tq - t; if (src < 0) src += 30;
            ulonglong2 qa = lds2(qsU + tq*4), qb = lds2(qsU + tq*4 + 2);
            ulonglong2 ka = lds2(ksU + src*4), kb = lds2(ksU + src*4 + 2);
            acc2[0] = fma2u(qa.x, ka.x, acc2[0]);
            acc2[1] = fma2u(qa.y, ka.y, acc2[1]);
            acc2[2] = fma2u(qb.x, kb.x, acc2[2]);
            acc2[3] = fma2u(qb.y, kb.y, acc2[3]);
        }
        u64 s2 = add2u(add2u(acc2[0], acc2[1]), add2u(acc2[2], acc2[3]));
        float sx, sy; unpack2(s2, sx, sy);
        mv = act ? (sx + sy) * 0.125f : -1e30f;
    }

    // ---- warp-parallel top-3 with first-index tie-break ----
    float wv0, wv1, wv2; int dl0, dl1, dl2;
    {
        float mrun = mv;
        #pragma unroll
        for (int p = 0; p < 3; p++) {
            float bv = mrun; int bi = lane;
            #pragma unroll
            for (int off = 16; off; off >>= 1) {
                float vo = __shfl_xor_sync(FULL, bv, off);
                int   io = __shfl_xor_sync(FULL, bi, off);
                if (vo > bv || (vo == bv && io < bi)) { bv = vo; bi = io; }
            }
            if (p == 0) { wv0 = bv; dl0 = bi; }
            else if (p == 1) { wv1 = bv; dl1 = bi; }
            else { wv2 = bv; dl2 = bi; }
            if (lane == bi) mrun = -1e30f;
        }
    }
    float e1 = expf(wv1 - wv0);
    float e2 = expf(wv2 - wv0);
    float inv = 1.f / (1.f + e1 + e2);
    float w0 = inv, w1 = e1 * inv, w2 = e2 * inv;

    // ---- delay aggregation via shuffles ----
    float agg[8];
    {
        int s0 = t + dl0; if (s0 >= 30) s0 -= 30;
        int s1 = t + dl1; if (s1 >= 30) s1 -= 30;
        int s2 = t + dl2; if (s2 >= 30) s2 -= 30;
        #pragma unroll
        for (int h = 0; h < 8; h++) {
            float a = w0 * __shfl_sync(FULL, v[h], s0);
            a      += w1 * __shfl_sync(FULL, v[h], s1);
            a      += w2 * __shfl_sync(FULL, v[h], s2);
            agg[h] = a;
        }
    }

    // ---- x1 = xe + agg @ Wo + bo ----
    u64 x1u[7];
    {
        const u64* sbo2 = reinterpret_cast<const u64*>(cbuf + OFF_BO);
        #pragma unroll
        for (int dp = 0; dp < 7; dp++) x1u[dp] = add2u(xe2[dp], sbo2[dp]);
        const u64* wo = reinterpret_cast<const u64*>(cbuf + OFF_WO);
        #pragma unroll
        for (int h = 0; h < 8; h++) {
            u64 a2 = dup2(agg[h]);
            const u64* wr = wo + h*8;
            #pragma unroll
            for (int dp = 0; dp < 7; dp++) x1u[dp] = fma2u(a2, wr[dp], x1u[dp]);
        }
    }

    // ---- series_decomp 1 ----
    const float fc0  = (t < 12) ? (float)(12 - t) : 0.f;
    const float fc29 = (t > 17) ? (float)(t - 17) : 0.f;
    const int hi   = (t + 12 > 29) ? 29 : t + 12;
    const int lom1 = t - 13;
    const int loix = (lom1 < 0) ? 0 : lom1;
    u64 xdu[7];
    #pragma unroll
    for (int dp = 0; dp < 7; dp++) {
        float vx, vy; unpack2(x1u[dp], vx, vy);
        float dx = decomp25(vx, lane, hi, loix, lom1, fc0, fc29);
        float dy = decomp25(vy, lane, hi, loix, lom1, fc0, fc29);
        xdu[dp] = pack2(dx, dy);
    }

    // ---- FFN: x2 = xd + gelu_exact(xd @ F1) @ F2 ----
    u64 x2u[7];
    {
        u64 y2[7] = {};
        const u64* f1 = reinterpret_cast<const u64*>(cbuf + OFF_F1);
        const u64* f2 = reinterpret_cast<const u64*>(cbuf + OFF_F2);
        #pragma unroll 5
        for (int f = 0; f < 50; f++) {
            const u64* r1 = f1 + f*8;
            u64 h2 = fma2u(xdu[0], r1[0], 0ULL);
            h2 = fma2u(xdu[1], r1[1], h2);
            h2 = fma2u(xdu[2], r1[2], h2);
            h2 = fma2u(xdu[3], r1[3], h2);
            h2 = fma2u(xdu[4], r1[4], h2);
            h2 = fma2u(xdu[5], r1[5], h2);
            h2 = fma2u(xdu[6], r1[6], h2);
            float hx, hy; unpack2(h2, hx, hy);
            float hs = hx + hy;
            float g = 0.5f * hs * (1.f + erff(hs * 0.70710678118654752f));
            u64 g2 = dup2(g);
            const u64* r2 = f2 + f*8;
            y2[0] = fma2u(g2, r2[0], y2[0]);
            y2[1] = fma2u(g2, r2[1], y2[1]);
            y2[2] = fma2u(g2, r2[2], y2[2]);
            y2[3] = fma2u(g2, r2[3], y2[3]);
            y2[4] = fma2u(g2, r2[4], y2[4]);
            y2[5] = fma2u(g2, r2[5], y2[5]);
            y2[6] = fma2u(g2, r2[6], y2[6]);
        }
        #pragma unroll
        for (int dp = 0; dp < 7; dp++) x2u[dp] = add2u(xdu[dp], y2[dp]);
    }

    // ---- series_decomp 2 + layernorm ----
    float x3x[7], x3y[7];
    #pragma unroll
    for (int dp = 0; dp < 7; dp++) {
        float vx, vy; unpack2(x2u[dp], vx, vy);
        x3x[dp] = decomp25(vx, lane, hi, loix, lom1, fc0, fc29);
        x3y[dp] = decomp25(vy, lane, hi, loix, lom1, fc0, fc29);
    }
    {
        float m = 0.f;
        #pragma unroll
        for (int dp = 0; dp < 7; dp++) m += x3x[dp] + x3y[dp];
        m *= (1.f / 14.f);
        float var = 0.f;
        #pragma unroll
        for (int dp = 0; dp < 7; dp++) {
            float dx = x3x[dp] - m, dy = x3y[dp] - m;
            var += dx * dx + dy * dy;
        }
        var *= (1.f / 14.f);
        float invs = rsqrtf(var + 1e-5f);
        #pragma unroll
        for (int dp = 0; dp < 7; dp++) {
            x3x[dp] = (x3x[dp] - m) * invs * cbuf[OFF_G + 2*dp]   + cbuf[OFF_B + 2*dp];
            x3y[dp] = (x3y[dp] - m) * invs * cbuf[OFF_G + 2*dp+1] + cbuf[OFF_B + 2*dp+1];
        }
    }

    // ---- DyConv: stage x3 pairs at [t*8+dp], accumulate over m (lane = l) ----
    __syncwarp();
    u64* x3sU = scrU;   // 240 u64 used
    if (act) {
        u64 p0 = pack2(x3x[0], x3y[0]), p1 = pack2(x3x[1], x3y[1]);
        u64 p2 = pack2(x3x[2], x3y[2]), p3 = pack2(x3x[3], x3y[3]);
        u64 p4 = pack2(x3x[4], x3y[4]), p5 = pack2(x3x[5], x3y[5]);
        u64 p6 = pack2(x3x[6], x3y[6]);
        *reinterpret_cast<ulonglong2*>(x3sU + t*8)     = make_ulonglong2(p0, p1);
        *reinterpret_cast<ulonglong2*>(x3sU + t*8 + 2) = make_ulonglong2(p2, p3);
        *reinterpret_cast<ulonglong2*>(x3sU + t*8 + 4) = make_ulonglong2(p4, p5);
        x3sU[t*8 + 6] = p6;
    }
    __syncwarp();
    u64 accd2[7];
    {
        u64 bias2 = dup2(sbdy[t]);
        #pragma unroll
        for (int dp = 0; dp < 7; dp++) accd2[dp] = bias2;
        #pragma unroll
        for (int m = 0; m < 30; m++) {
            u64 wm2 = dup2(sWdy[m*30 + t]);
            const u64* xb = x3sU + m*8;
            ulonglong2 xa = lds2(xb), xbv = lds2(xb+2), xc = lds2(xb+4);
            u64 x6 = xb[6];
            accd2[0] = fma2u(xa.x, wm2, accd2[0]);
            accd2[1] = fma2u(xa.y, wm2, accd2[1]);
            accd2[2] = fma2u(xbv.x, wm2, accd2[2]);
            accd2[3] = fma2u(xbv.y, wm2, accd2[3]);
            accd2[4] = fma2u(xc.x, wm2, accd2[4]);
            accd2[5] = fma2u(xc.y, wm2, accd2[5]);
            accd2[6] = fma2u(x6,   wm2, accd2[6]);
        }
    }

    // ---- dy = relu(adj @ h2) -> g_f ----
    {
        float* fo = g_f + (size_t)smp * 420;
        const u64* adj = reinterpret_cast<const u64*>(cbuf + OFF_ADJ);
        #pragma unroll
        for (int i = 0; i < 14; i++) {
            const u64* ar = adj + i*8;
            u64 acc = fma2u(ar[0], accd2[0], 0ULL);
            acc = fma2u(ar[1], accd2[1], acc);
            acc = fma2u(ar[2], accd2[2], acc);
            acc = fma2u(ar[3], accd2[3], acc);
            acc = fma2u(ar[4], accd2[4], acc);
            acc = fma2u(ar[5], accd2[5], acc);
            acc = fma2u(ar[6], accd2[6], acc);
            float ax, ay; unpack2(acc, ax, ay);
            if (act) fo[i*30 + t] = fmaxf(ax + ay, 0.f);
        }
    }
}

// ============================================================================
// Kernel B (tensor, pre-split hi/lo): hh = relu(f @ W1 + b1)
// M=65536, K=420 (pad 448), N=256. BM=128, BN=64 (grid.y=4), BK=16.
// ============================================================================
__global__ __launch_bounds__(256) void kB(const float* __restrict__ W1,
                                          const float* __restrict__ b1)
{
    __shared__ __align__(16) float2 As2[128][20];   // (hi, lo) per element
    __shared__ __align__(16) float2 Bs2[64][20];
    const int tid = threadIdx.x;
    const int lane = tid & 31, wid = tid >> 5;
    const int wm = wid >> 1, wn = wid & 1;
    const size_t mbase = (size_t)blockIdx.x * 128;
    const int nbase = blockIdx.y * 64;
    float c[2][4][4] = {};

    for (int k0 = 0; k0 < 448; k0 += 16) {
        // A stage: 128x16 from g_f (zero-pad past 420), split at load
        {
            int m = tid >> 1;
            const float4* gr = reinterpret_cast<const float4*>(g_f + (mbase + m) * 420);
            #pragma unroll
            for (int j = 0; j < 2; j++) {
                int kq = (k0 >> 2) + (tid & 1) * 2 + j;
                float4 vv = (kq < 105) ? gr[kq] : make_float4(0.f,0.f,0.f,0.f);
                int cb = (tid & 1) * 8 + j * 4;
                unsigned hi, lo;
                split_tf32(vv.x, hi, lo); As2[m][cb+0] = make_float2(__uint_as_float(hi), __uint_as_float(lo));
                split_tf32(vv.y, hi, lo); As2[m][cb+1] = make_float2(__uint_as_float(hi), __uint_as_float(lo));
                split_tf32(vv.z, hi, lo); As2[m][cb+2] = make_float2(__uint_as_float(hi), __uint_as_float(lo));
                split_tf32(vv.w, hi, lo); As2[m][cb+3] = make_float2(__uint_as_float(hi), __uint_as_float(lo));
            }
        }
        // B stage: 16x64 of W1, transposed to Bs2[n][k], split at load
        {
            int kl = tid >> 4;
            int gk = k0 + kl;
            int n4 = (tid & 15) * 4;
            float4 vv = make_float4(0.f,0.f,0.f,0.f);
            if (gk < 420)
                vv = *reinterpret_cast<const float4*>(W1 + (size_t)gk*256 + nbase + n4);
            unsigned hi, lo;
            split_tf32(vv.x, hi, lo); Bs2[n4+0][kl] = make_float2(__uint_as_float(hi), __uint_as_float(lo));
            split_tf32(vv.y, hi, lo); Bs2[n4+1][kl] = make_float2(__uint_as_float(hi), __uint_as_float(lo));
            split_tf32(vv.z, hi, lo); Bs2[n4+2][kl] = make_float2(__uint_as_float(hi), __uint_as_float(lo));
            split_tf32(vv.w, hi, lo); Bs2[n4+3][kl] = make_float2(__uint_as_float(hi), __uint_as_float(lo));
        }
        __syncthreads();
        #pragma unroll
        for (int ks = 0; ks < 2; ks++) {
            int kk = ks * 8;
            unsigned ah[2][4], al[2][4], bh[4][2], bl[4][2];
            #pragma unroll
            for (int mt = 0; mt < 2; mt++) {
                int r = wm*32 + mt*16 + (lane>>2);
                float2 e;
                e = As2[r  ][kk + (lane&3)    ]; ah[mt][0] = __float_as_uint(e.x); al[mt][0] = __float_as_uint(e.y);
                e = As2[r+8][kk + (lane&3)    ]; ah[mt][1] = __float_as_uint(e.x); al[mt][1] = __float_as_uint(e.y);
                e = As2[r  ][kk + (lane&3) + 4]; ah[mt][2] = __float_as_uint(e.x); al[mt][2] = __float_as_uint(e.y);
                e = As2[r+8][kk + (lane&3) + 4]; ah[mt][3] = __float_as_uint(e.x); al[mt][3] = __float_as_uint(e.y);
            }
            #pragma unroll
            for (int nt = 0; nt < 4; nt++) {
                int nn = wn*32 + nt*8 + (lane>>2);
                float2 e;
                e = Bs2[nn][kk + (lane&3)    ]; bh[nt][0] = __float_as_uint(e.x); bl[nt][0] = __float_as_uint(e.y);
                e = Bs2[nn][kk + (lane&3) + 4]; bh[nt][1] = __float_as_uint(e.x); bl[nt][1] = __float_as_uint(e.y);
            }
            #pragma unroll
            for (int mt = 0; mt < 2; mt++)
                #pragma unroll
                for (int nt = 0; nt < 4; nt++) {
                    mma_tf32(c[mt][nt], ah[mt], bh[nt]);
                    mma_tf32(c[mt][nt], ah[mt], bl[nt]);
                    mma_tf32(c[mt][nt], al[mt], bh[nt]);
                }
        }
        __syncthreads();
    }
    #pragma unroll
    for (int mt = 0; mt < 2; mt++) {
        int r0 = wm*32 + mt*16 + (lane>>2);
        #pragma unroll
        for (int nt = 0; nt < 4; nt++) {
            int cl = nbase + wn*32 + nt*8 + 2*(lane&3);
            float b0 = b1[cl], b1v = b1[cl+1];
            float2 lo = make_float2(fmaxf(c[mt][nt][0] + b0, 0.f), fmaxf(c[mt][nt][1] + b1v, 0.f));
            float2 hi = make_float2(fmaxf(c[mt][nt][2] + b0, 0.f), fmaxf(c[mt][nt][3] + b1v, 0.f));
            *reinterpret_cast<float2*>(g_hh + (mbase + r0    ) * 256 + cl) = lo;
            *reinterpret_cast<float2*>(g_hh + (mbase + r0 + 8) * 256 + cl) = hi;
        }
    }
}

// ============================================================================
// Kernel C (tensor, pre-split, fused LN head): hr = [hh|f]@[W2;Wres]+b2+bres,
// then out = LN64(hr) @ W3 + b3 from register fragments. K=676 (pad 704), BK=16.
// ============================================================================
__global__ __launch_bounds__(256) void kC(const float* __restrict__ W2,
                                          const float* __restrict__ b2,
                                          const float* __restrict__ Wres,
                                          const float* __restrict__ bres,
                                          const float* __restrict__ g_ln,
                                          const float* __restrict__ b_ln,
                                          const float* __restrict__ W3,
                                          const float* __restrict__ b3,
                                          float* __restrict__ out)
{
    __shared__ __align__(16) float2 As2[128][20];
    __shared__ __align__(16) float2 Bs2[64][20];
    __shared__ float sbb[64];        // b2+bres
    __shared__ float sgw[64];        // g_ln*W3
    __shared__ float sp[128][2][3];  // per-row half partials (sv, sq, sg)
    __shared__ float sconst[2];      // G, cb
    const int tid = threadIdx.x;
    const int lane = tid & 31, wid = tid >> 5;
    const int wm = wid >> 1, wn = wid & 1;
    const size_t mbase = (size_t)blockIdx.x * 128;
    float c[2][4][4] = {};

    if (tid < 64) {
        sbb[tid] = b2[tid] + bres[tid];
        sgw[tid] = g_ln[tid] * W3[tid];
    }

    for (int k0 = 0; k0 < 704; k0 += 16) {
        // A stage: concat [hh(256) | f(420)], split at load
        {
            int m = tid >> 1;
            const float* hrow = g_hh + (mbase + m) * 256;
            const float* frow = g_f  + (mbase + m) * 420;
            #pragma unroll
            for (int j = 0; j < 2; j++) {
                int gk = k0 + (tid & 1) * 8 + j * 4;
                float4 vv = make_float4(0.f,0.f,0.f,0.f);
                if (gk < 256) vv = *reinterpret_cast<const float4*>(hrow + gk);
                else { int kf = gk - 256; if (kf < 420) vv = *reinterpret_cast<const float4*>(frow + kf); }
                int cb = (tid & 1) * 8 + j * 4;
                unsigned hi, lo;
                split_tf32(vv.x, hi, lo); As2[m][cb+0] = make_float2(__uint_as_float(hi), __uint_as_float(lo));
                split_tf32(vv.y, hi, lo); As2[m][cb+1] = make_float2(__uint_as_float(hi), __uint_as_float(lo));
                split_tf32(vv.z, hi, lo); As2[m][cb+2] = make_float2(__uint_as_float(hi), __uint_as_float(lo));
                split_tf32(vv.w, hi, lo); As2[m][cb+3] = make_float2(__uint_as_float(hi), __uint_as_float(lo));
            }
        }
        // B stage: concat [W2(256x64); Wres(420x64)], transposed, split at load
        {
            int kl = tid >> 4;
            int gk = k0 + kl;
            int n4 = (tid & 15) * 4;
            float4 vv = make_float4(0.f,0.f,0.f,0.f);
            if (gk < 256) vv = *reinterpret_cast<const float4*>(W2 + (size_t)gk*64 + n4);
            else { int kf = gk - 256; if (kf < 420) vv = *reinterpret_cast<const float4*>(Wres + (size_t)kf*64 + n4); }
            unsigned hi, lo;
            split_tf32(vv.x, hi, lo); Bs2[n4+0][kl] = make_float2(__uint_as_float(hi), __uint_as_float(lo));
            split_tf32(vv.y, hi, lo); Bs2[n4+1][kl] = make_float2(__uint_as_float(hi), __uint_as_float(lo));
            split_tf32(vv.z, hi, lo); Bs2[n4+2][kl] = make_float2(__uint_as_float(hi), __uint_as_float(lo));
            split_tf32(vv.w, hi, lo); Bs2[n4+3][kl] = make_float2(__uint_as_float(hi), __uint_as_float(lo));
        }
        __syncthreads();
        #pragma unroll
        for (int ks = 0; ks < 2; ks++) {
            int kk = ks * 8;
            unsigned ah[2][4], al[2][4], bh[4][2], bl[4][2];
            #pragma unroll
            for (int mt = 0; mt < 2; mt++) {
                int r = wm*32 + mt*16 + (lane>>2);
                float2 e;
                e = As2[r  ][kk + (lane&3)    ]; ah[mt][0] = __float_as_uint(e.x); al[mt][0] = __float_as_uint(e.y);
                e = As2[r+8][kk + (lane&3)    ]; ah[mt][1] = __float_as_uint(e.x); al[mt][1] = __float_as_uint(e.y);
                e = As2[r  ][kk + (lane&3) + 4]; ah[mt][2] = __float_as_uint(e.x); al[mt][2] = __float_as_uint(e.y);
                e = As2[r+8][kk + (lane&3) + 4]; ah[mt][3] = __float_as_uint(e.x); al[mt][3] = __float_as_uint(e.y);
            }
            #pragma unroll
            for (int nt = 0; nt < 4; nt++) {
                int nn = wn*32 + nt*8 + (lane>>2);
                float2 e;
                e = Bs2[nn][kk + (lane&3)    ]; bh[nt][0] = __float_as_uint(e.x); bl[nt][0] = __float_as_uint(e.y);
                e = Bs2[nn][kk + (lane&3) + 4]; bh[nt][1] = __float_as_uint(e.x); bl[nt][1] = __float_as_uint(e.y);
            }
            #pragma unroll
            for (int mt = 0; mt < 2; mt++)
                #pragma unroll
                for (int nt = 0; nt < 4; nt++) {
                    mma_tf32(c[mt][nt], ah[mt], bh[nt]);
                    mma_tf32(c[mt][nt], ah[mt], bl[nt]);
                    mma_tf32(c[mt][nt], al[mt], bh[nt]);
                }
        }
        __syncthreads();
    }

    // ---- fused epilogue: partial LN sums per (row, wn-half) ----
    #pragma unroll
    for (int mt = 0; mt < 2; mt++) {
        #pragma unroll
        for (int rb = 0; rb < 2; rb++) {
            float sv = 0.f, sq = 0.f, sgd = 0.f;
            #pragma unroll
            for (int nt = 0; nt < 4; nt++) {
                int cl = wn*32 + nt*8 + 2*(lane&3);
                float v0 = c[mt][nt][2*rb]     + sbb[cl];
                float v1 = c[mt][nt][2*rb + 1] + sbb[cl+1];
                sv += v0 + v1;
                sq += v0*v0 + v1*v1;
                sgd += v0*sgw[cl] + v1*sgw[cl+1];
            }
            sv += __shfl_xor_sync(FULL, sv, 1);
            sq += __shfl_xor_sync(FULL, sq, 1);
            sgd += __shfl_xor_sync(FULL, sgd, 1);
            sv += __shfl_xor_sync(FULL, sv, 2);
            sq += __shfl_xor_sync(FULL, sq, 2);
            sgd += __shfl_xor_sync(FULL, sgd, 2);
            if ((lane & 3) == 0) {
                int row = wm*32 + mt*16 + rb*8 + (lane>>2);
                sp[row][wn][0] = sv;
                sp[row][wn][1] = sq;
                sp[row][wn][2] = sgd;
            }
        }
    }
    if (tid == 0) {
        float G = 0.f, cb = b3[0];
        for (int d = 0; d < 64; d++) { G += sgw[d]; cb += b_ln[d] * W3[d]; }
        sconst[0] = G; sconst[1] = cb;
    }
    __syncthreads();
    if (tid < 128) {
        int row = tid;
        float sv  = sp[row][0][0] + sp[row][1][0];
        float sq  = sp[row][0][1] + sp[row][1][1];
        float sgd = sp[row][0][2] + sp[row][1][2];
        float m = sv * (1.f / 64.f);
        float var = sq * (1.f / 64.f) - m * m;
        float invs = rsqrtf(var + 1e-5f);
        out[mbase + row] = invs * (sgd - m * sconst[0]) + sconst[1];
    }
}

// ============================================================================
extern "C" void kernel_launch(void* const* d_in, const int* in_sizes, int n_in,
                              void* d_out, int out_size)
{
    (void)in_sizes; (void)n_in; (void)out_size;
    const float* x = (const float*)d_in[0];

    kPrep<<<1, 256>>>(
        (const float*)d_in[1],  (const float*)d_in[2],
        (const float*)d_in[3],  (const float*)d_in[4],
        (const float*)d_in[5],  (const float*)d_in[6],
        (const float*)d_in[7],  (const float*)d_in[8],
        (const float*)d_in[9],  (const float*)d_in[10],
        (const float*)d_in[11], (const float*)d_in[12],
        (const float*)d_in[13], (const float*)d_in[14],
        (const float*)d_in[17]);

    void* csym = nullptr; void* gsym = nullptr;
    cudaGetSymbolAddress(&csym, cbuf);
    cudaGetSymbolAddress(&gsym, g_wbuf);
    cudaMemcpyAsync(csym, gsym, CW_TOTAL * sizeof(float),
                    cudaMemcpyDeviceToDevice, 0);

    kA<<<BATCH / 8, 256>>>(x, (const float*)d_in[15], (const float*)d_in[16]);

    kB<<<dim3(BATCH / 128, 4), 256>>>((const float*)d_in[18], (const float*)d_in[19]);

    kC<<<BATCH / 128, 256>>>((const float*)d_in[20], (const float*)d_in[21],
                             (const float*)d_in[22], (const float*)d_in[23],
                             (const float*)d_in[24], (const float*)d_in[25],
                             (const float*)d_in[26], (const float*)d_in[27],
                             (float*)d_out);
}

// round 11
// speedup vs baseline: 1.2309x; 1.2309x over previous
#include <cuda_runtime.h>
#include <math.h>

#define BATCH 65536
#define FULL 0xffffffffu

typedef unsigned long long u64;

// -------- device scratch (allocation-free rule: __device__ globals) --------
__device__ float g_f [(size_t)BATCH * 420];   // DyConv output
__device__ float g_hh[(size_t)BATCH * 256];   // relu(f@W1+b1)
__device__ float g_hr[(size_t)BATCH * 64];    // hh@W2 + f@Wres + b2 + bres

// ---------------- packed f32x2 ops on b64 registers ----------------
__device__ __forceinline__ u64 pack2(float x, float y) {
    u64 r; asm("mov.b64 %0, {%1, %2};" : "=l"(r) : "f"(x), "f"(y)); return r;
}
__device__ __forceinline__ u64 dup2(float s) { return pack2(s, s); }
__device__ __forceinline__ void unpack2(u64 v, float& x, float& y) {
    asm("mov.b64 {%0, %1}, %2;" : "=f"(x), "=f"(y) : "l"(v));
}
__device__ __forceinline__ u64 fma2u(u64 a, u64 b, u64 c) {
    u64 d; asm("fma.rn.f32x2 %0, %1, %2, %3;" : "=l"(d) : "l"(a), "l"(b), "l"(c)); return d;
}
__device__ __forceinline__ u64 add2u(u64 a, u64 b) {
    u64 d; asm("add.rn.f32x2 %0, %1, %2;" : "=l"(d) : "l"(a), "l"(b)); return d;
}
__device__ __forceinline__ ulonglong2 lds2(const u64* p) {
    return *reinterpret_cast<const ulonglong2*>(p);
}

// ---------------- tf32 helpers (3xTF32 compensated GEMM) ----------------
__device__ __forceinline__ void split_tf32(float x, unsigned& hi, unsigned& lo) {
    asm("cvt.rna.tf32.f32 %0, %1;" : "=r"(hi) : "f"(x));
    float r = x - __uint_as_float(hi);
    asm("cvt.rna.tf32.f32 %0, %1;" : "=r"(lo) : "f"(r));
}
__device__ __forceinline__ void mma_tf32(float* c, const unsigned* a, const unsigned* b) {
    asm volatile(
        "mma.sync.aligned.m16n8k8.row.col.f32.tf32.tf32.f32 "
        "{%0,%1,%2,%3},{%4,%5,%6,%7},{%8,%9},{%0,%1,%2,%3};"
        : "+f"(c[0]), "+f"(c[1]), "+f"(c[2]), "+f"(c[3])
        : "r"(a[0]), "r"(a[1]), "r"(a[2]), "r"(a[3]), "r"(b[0]), "r"(b[1]));
}

// ---- shuffle-scan series_decomp helper (replicate-pad MA-25) ----
__device__ __forceinline__ float decomp25(float val, int lane, int hi, int loix,
                                          int lom1, float fc0, float fc29) {
    float cs = val;
    #pragma unroll
    for (int off = 1; off < 32; off <<= 1) {
        float o = __shfl_up_sync(FULL, cs, off);
        if (lane >= off) cs += o;
    }
    float cshi = __shfl_sync(FULL, cs, hi);
    float cslo = __shfl_sync(FULL, cs, loix);
    float ssum = cshi - ((lom1 >= 0) ? cslo : 0.f);
    float x0  = __shfl_sync(FULL, val, 0);
    float x29 = __shfl_sync(FULL, val, 29);
    return val - (ssum + fc0 * x0 + fc29 * x29) * (1.f / 25.f);
}

// ---- warp-parallel top-3 with first-index tie-break, then softmax ----
__device__ __forceinline__ void top3softmax(float mv, int lane,
                                            float& w0, float& w1, float& w2,
                                            int& dl0, int& dl1, int& dl2) {
    float wv0, wv1, wv2;
    float mrun = mv;
    #pragma unroll
    for (int p = 0; p < 3; p++) {
        float bv = mrun; int bi = lane;
        #pragma unroll
        for (int off = 16; off; off >>= 1) {
            float vo = __shfl_xor_sync(FULL, bv, off);
            int   io = __shfl_xor_sync(FULL, bi, off);
            if (vo > bv || (vo == bv && io < bi)) { bv = vo; bi = io; }
        }
        if (p == 0) { wv0 = bv; dl0 = bi; }
        else if (p == 1) { wv1 = bv; dl1 = bi; }
        else { wv2 = bv; dl2 = bi; }
        if (lane == bi) mrun = -1e30f;
    }
    float e1 = expf(wv1 - wv0);
    float e2 = expf(wv2 - wv0);
    float inv = 1.f / (1.f + e1 + e2);
    w0 = inv; w1 = e1 * inv; w2 = e2 * inv;
}

// ---- circular correlation for one sample (lane = tau) ----
__device__ __forceinline__ float corr30(const u64* qsU, const u64* ksU,
                                        int t, bool act) {
    u64 acc2[4] = {};
    #pragma unroll
    for (int tq = 0; tq < 30; tq++) {
        int src = tq - t; if (src < 0) src += 30;
        ulonglong2 qa = lds2(qsU + tq*4), qb = lds2(qsU + tq*4 + 2);
        ulonglong2 ka = lds2(ksU + src*4), kb = lds2(ksU + src*4 + 2);
        acc2[0] = fma2u(qa.x, ka.x, acc2[0]);
        acc2[1] = fma2u(qa.y, ka.y, acc2[1]);
        acc2[2] = fma2u(qb.x, kb.x, acc2[2]);
        acc2[3] = fma2u(qb.y, kb.y, acc2[3]);
    }
    u64 s2 = add2u(add2u(acc2[0], acc2[1]), add2u(acc2[2], acc2[3]));
    float sx, sy; unpack2(s2, sx, sy);
    return act ? (sx + sy) * 0.125f : -1e30f;
}

// ============================================================================
// Kernel A: register-resident per-sample pipeline, FFMA2, 2 SAMPLES PER WARP
// (weight-tile LDS amortized across both samples). Lane t in [0,30) = time.
// ============================================================================
__global__ __launch_bounds__(256, 2) void kA(
    const float* __restrict__ x,
    const float* __restrict__ W_emb, const float* __restrict__ b_emb,
    const float* __restrict__ Wq, const float* __restrict__ bq,
    const float* __restrict__ Wk, const float* __restrict__ bk,
    const float* __restrict__ Wv, const float* __restrict__ bv,
    const float* __restrict__ Wo, const float* __restrict__ bo,
    const float* __restrict__ Wff1, const float* __restrict__ Wff2,
    const float* __restrict__ gnorm, const float* __restrict__ bnorm,
    const float* __restrict__ Wdy, const float* __restrict__ bdy,
    const float* __restrict__ channels)
{
    // 8-slot padded pair tiles for LDS.128
    __shared__ __align__(16) float2 sWeP[336];   // [(ci*3+tp)*8+op], op<7 valid
    __shared__ __align__(16) float  sbe[14];
    __shared__ __align__(16) float  sWq[112], sWk[112], sWv[112];   // [d*8+h]
    __shared__ __align__(16) float  sbq[8], sbk[8], sbv[8];
    __shared__ __align__(16) float2 sWoP[64];    // [h*8+dp], dp<7 valid
    __shared__ __align__(16) float  sbo[14];
    __shared__ __align__(16) float2 sF1P[400];   // [f*8+dp]
    __shared__ __align__(16) float2 sF2P[400];   // [f*8+dp]
    __shared__ __align__(16) float  sg[14], sb[14];
    __shared__ __align__(16) float  sWdy[900], sbdy[32];
    __shared__ __align__(16) float2 sAdjP[112];  // [i*8+jp], jp<7 valid
    __shared__ __align__(16) float  scr[8][960]; // per-warp scratch (3840B)

    const int tid = threadIdx.x;
    for (int i = tid; i < 336; i += 256) {
        int ct = i >> 3, op = i & 7;
        float a = 0.f, b = 0.f;
        if (op < 7) { a = W_emb[(2*op)*42 + ct]; b = W_emb[(2*op+1)*42 + ct]; }
        sWeP[i] = make_float2(a, b);
    }
    for (int i = tid; i < 112; i += 256) { sWq[i]=Wq[i]; sWk[i]=Wk[i]; sWv[i]=Wv[i]; }
    for (int i = tid; i < 64; i += 256) {
        int h = i >> 3, dp = i & 7;
        float a = 0.f, b = 0.f;
        if (dp < 7) { a = Wo[h*14 + 2*dp]; b = Wo[h*14 + 2*dp + 1]; }
        sWoP[i] = make_float2(a, b);
    }
    for (int i = tid; i < 400; i += 256) {
        int f = i >> 3, dp = i & 7;
        float a1 = 0.f, b1v = 0.f, a2 = 0.f, b2v = 0.f;
        if (dp < 7) {
            a1 = Wff1[(2*dp)*50 + f]; b1v = Wff1[(2*dp+1)*50 + f];
            a2 = Wff2[f*14 + 2*dp];   b2v = Wff2[f*14 + 2*dp + 1];
        }
        sF1P[i] = make_float2(a1, b1v);
        sF2P[i] = make_float2(a2, b2v);
    }
    for (int i = tid; i < 900; i += 256) sWdy[i] = Wdy[i];
    if (tid < 30) sbdy[tid] = bdy[tid];
    if (tid < 14) { sbe[tid]=b_emb[tid]; sbo[tid]=bo[tid]; sg[tid]=gnorm[tid]; sb[tid]=bnorm[tid]; }
    if (tid < 8)  { sbq[tid]=bq[tid]; sbk[tid]=bk[tid]; sbv[tid]=bv[tid]; }
    if (tid < 14) {
        const float* row = channels + tid * 14;
        float mx = -1e30f;
        #pragma unroll
        for (int j = 0; j < 14; j++) mx = fmaxf(mx, row[j]);
        float s = 0.f;
        #pragma unroll
        for (int j = 0; j < 14; j++) s += expf(row[j] - mx);
        float inv = 1.f / s;
        #pragma unroll
        for (int j = 0; j < 7; j++)
            sAdjP[tid*8 + j] = make_float2(expf(row[2*j] - mx) * inv,
                                           expf(row[2*j+1] - mx) * inv);
        sAdjP[tid*8 + 7] = make_float2(0.f, 0.f);
    }
    __syncthreads();

    const int w    = tid >> 5;
    const int lane = tid & 31;
    const int t    = (lane < 30) ? lane : 0;
    const bool act = (lane < 30);
    const int smpA = blockIdx.x * 16 + w * 2;
    u64* scrU = reinterpret_cast<u64*>(scr[w]);

    // ---- coalesced stage of both samples' x ----
    {
        const float4* xpA = reinterpret_cast<const float4*>(x + (size_t)smpA * 420);
        const float4* xpB = reinterpret_cast<const float4*>(x + (size_t)(smpA+1) * 420);
        float4* sp = reinterpret_cast<float4*>(scr[w]);
        #pragma unroll
        for (int i = lane; i < 105; i += 32) { sp[i] = xpA[i]; sp[105 + i] = xpB[i]; }
    }
    __syncwarp();
    float xrA[14], xrB[14];
    #pragma unroll
    for (int d = 0; d < 14; d++) {
        xrA[d] = scr[w][t*14 + d];
        xrB[d] = scr[w][420 + t*14 + d];
    }
    __syncwarp();

    // ---- Conv1d embed (kernel 3, zero pad): weights loaded once per warp ----
    u64 xeA[7], xeB[7];
    {
        const u64* sbe2 = reinterpret_cast<const u64*>(sbe);
        #pragma unroll
        for (int op = 0; op < 7; op++) { xeA[op] = sbe2[op]; xeB[op] = sbe2[op]; }
        const u64* we = reinterpret_cast<const u64*>(sWeP);
        #pragma unroll
        for (int ci = 0; ci < 14; ci++) {
            float upA = __shfl_up_sync(FULL, xrA[ci], 1);
            float dnA = __shfl_down_sync(FULL, xrA[ci], 1);
            float upB = __shfl_up_sync(FULL, xrB[ci], 1);
            float dnB = __shfl_down_sync(FULL, xrB[ci], 1);
            float tapA[3] = { (lane > 0) ? upA : 0.f, xrA[ci], (lane < 29) ? dnA : 0.f };
            float tapB[3] = { (lane > 0) ? upB : 0.f, xrB[ci], (lane < 29) ? dnB : 0.f };
            #pragma unroll
            for (int tp = 0; tp < 3; tp++) {
                u64 xa = dup2(tapA[tp]), xb = dup2(tapB[tp]);
                const u64* wr = we + (ci*3 + tp) * 8;
                ulonglong2 w0 = lds2(wr), w1 = lds2(wr+2), w2 = lds2(wr+4);
                u64 w6 = wr[6];
                xeA[0] = fma2u(xa, w0.x, xeA[0]); xeB[0] = fma2u(xb, w0.x, xeB[0]);
                xeA[1] = fma2u(xa, w0.y, xeA[1]); xeB[1] = fma2u(xb, w0.y, xeB[1]);
                xeA[2] = fma2u(xa, w1.x, xeA[2]); xeB[2] = fma2u(xb, w1.x, xeB[2]);
                xeA[3] = fma2u(xa, w1.y, xeA[3]); xeB[3] = fma2u(xb, w1.y, xeB[3]);
                xeA[4] = fma2u(xa, w2.x, xeA[4]); xeB[4] = fma2u(xb, w2.x, xeB[4]);
                xeA[5] = fma2u(xa, w2.y, xeA[5]); xeB[5] = fma2u(xb, w2.y, xeB[5]);
                xeA[6] = fma2u(xa, w6,   xeA[6]); xeB[6] = fma2u(xb, w6,   xeB[6]);
            }
        }
    }

    // ---- QKV (packed head pairs; weight LDS shared across samples) ----
    u64 qA[4], kA_[4], vA[4], qB[4], kB_[4], vB[4];
    {
        const u64* bq2 = reinterpret_cast<const u64*>(sbq);
        const u64* bk2 = reinterpret_cast<const u64*>(sbk);
        const u64* bv2 = reinterpret_cast<const u64*>(sbv);
        #pragma unroll
        for (int hp = 0; hp < 4; hp++) {
            qA[hp]=bq2[hp]; kA_[hp]=bk2[hp]; vA[hp]=bv2[hp];
            qB[hp]=bq2[hp]; kB_[hp]=bk2[hp]; vB[hp]=bv2[hp];
        }
        const u64* wq2 = reinterpret_cast<const u64*>(sWq);
        const u64* wk2 = reinterpret_cast<const u64*>(sWk);
        const u64* wv2 = reinterpret_cast<const u64*>(sWv);
        #pragma unroll
        for (int dp = 0; dp < 7; dp++) {
            float ax, ay, bx, by;
            unpack2(xeA[dp], ax, ay);
            unpack2(xeB[dp], bx, by);
            float sA[2] = { ax, ay }, sB[2] = { bx, by };
            #pragma unroll
            for (int half = 0; half < 2; half++) {
                int d = 2*dp + half;
                u64 xa = dup2(sA[half]), xb = dup2(sB[half]);
                ulonglong2 qa = lds2(wq2 + d*4), qb = lds2(wq2 + d*4 + 2);
                ulonglong2 ka = lds2(wk2 + d*4), kb = lds2(wk2 + d*4 + 2);
                ulonglong2 va = lds2(wv2 + d*4), vb = lds2(wv2 + d*4 + 2);
                qA[0] = fma2u(xa, qa.x, qA[0]); qB[0] = fma2u(xb, qa.x, qB[0]);
                qA[1] = fma2u(xa, qa.y, qA[1]); qB[1] = fma2u(xb, qa.y, qB[1]);
                qA[2] = fma2u(xa, qb.x, qA[2]); qB[2] = fma2u(xb, qb.x, qB[2]);
                qA[3] = fma2u(xa, qb.y, qA[3]); qB[3] = fma2u(xb, qb.y, qB[3]);
                kA_[0] = fma2u(xa, ka.x, kA_[0]); kB_[0] = fma2u(xb, ka.x, kB_[0]);
                kA_[1] = fma2u(xa, ka.y, kA_[1]); kB_[1] = fma2u(xb, ka.y, kB_[1]);
                kA_[2] = fma2u(xa, kb.x, kA_[2]); kB_[2] = fma2u(xb, kb.x, kB_[2]);
                kA_[3] = fma2u(xa, kb.y, kA_[3]); kB_[3] = fma2u(xb, kb.y, kB_[3]);
                vA[0] = fma2u(xa, va.x, vA[0]); vB[0] = fma2u(xb, va.x, vB[0]);
                vA[1] = fma2u(xa, va.y, vA[1]); vB[1] = fma2u(xb, va.y, vB[1]);
                vA[2] = fma2u(xa, vb.x, vA[2]); vB[2] = fma2u(xb, vb.x, vB[2]);
                vA[3] = fma2u(xa, vb.y, vA[3]); vB[3] = fma2u(xb, vb.y, vB[3]);
            }
        }
    }

    // stage q,k for both samples: [t*4 + hp] (u64)
    u64* qsA = scrU;          // 120
    u64* ksA = scrU + 120;    // 120
    u64* qsB = scrU + 240;    // 120
    u64* ksB = scrU + 360;    // 120
    if (act) {
        *reinterpret_cast<ulonglong2*>(qsA + t*4)     = make_ulonglong2(qA[0], qA[1]);
        *reinterpret_cast<ulonglong2*>(qsA + t*4 + 2) = make_ulonglong2(qA[2], qA[3]);
        *reinterpret_cast<ulonglong2*>(ksA + t*4)     = make_ulonglong2(kA_[0], kA_[1]);
        *reinterpret_cast<ulonglong2*>(ksA + t*4 + 2) = make_ulonglong2(kA_[2], kA_[3]);
        *reinterpret_cast<ulonglong2*>(qsB + t*4)     = make_ulonglong2(qB[0], qB[1]);
        *reinterpret_cast<ulonglong2*>(qsB + t*4 + 2) = make_ulonglong2(qB[2], qB[3]);
        *reinterpret_cast<ulonglong2*>(ksB + t*4)     = make_ulonglong2(kB_[0], kB_[1]);
        *reinterpret_cast<ulonglong2*>(ksB + t*4 + 2) = make_ulonglong2(kB_[2], kB_[3]);
    }
    __syncwarp();

    // ---- correlation + top-3 + softmax, per sample ----
    float mvA = corr30(qsA, ksA, t, act);
    float mvB = corr30(qsB, ksB, t, act);
    float w0A, w1A, w2A, w0B, w1B, w2B;
    int dl0A, dl1A, dl2A, dl0B, dl1B, dl2B;
    top3softmax(mvA, lane, w0A, w1A, w2A, dl0A, dl1A, dl2A);
    top3softmax(mvB, lane, w0B, w1B, w2B, dl0B, dl1B, dl2B);

    // ---- delay aggregation via u64 shuffles ----
    u64 aggA[4], aggB[4];
    {
        int s0 = t + dl0A; if (s0 >= 30) s0 -= 30;
        int s1 = t + dl1A; if (s1 >= 30) s1 -= 30;
        int s2 = t + dl2A; if (s2 >= 30) s2 -= 30;
        u64 c0 = dup2(w0A), c1 = dup2(w1A), c2 = dup2(w2A);
        #pragma unroll
        for (int hp = 0; hp < 4; hp++) {
            u64 y0 = __shfl_sync(FULL, vA[hp], s0);
            u64 y1 = __shfl_sync(FULL, vA[hp], s1);
            u64 y2 = __shfl_sync(FULL, vA[hp], s2);
            aggA[hp] = fma2u(c0, y0, fma2u(c1, y1, fma2u(c2, y2, 0ULL)));
        }
    }
    {
        int s0 = t + dl0B; if (s0 >= 30) s0 -= 30;
        int s1 = t + dl1B; if (s1 >= 30) s1 -= 30;
        int s2 = t + dl2B; if (s2 >= 30) s2 -= 30;
        u64 c0 = dup2(w0B), c1 = dup2(w1B), c2 = dup2(w2B);
        #pragma unroll
        for (int hp = 0; hp < 4; hp++) {
            u64 y0 = __shfl_sync(FULL, vB[hp], s0);
            u64 y1 = __shfl_sync(FULL, vB[hp], s1);
            u64 y2 = __shfl_sync(FULL, vB[hp], s2);
            aggB[hp] = fma2u(c0, y0, fma2u(c1, y1, fma2u(c2, y2, 0ULL)));
        }
    }

    // ---- x1 = xe + agg @ Wo + bo (weight LDS shared) ----
    u64 x1A[7], x1B[7];
    {
        const u64* sbo2 = reinterpret_cast<const u64*>(sbo);
        #pragma unroll
        for (int dp = 0; dp < 7; dp++) {
            x1A[dp] = add2u(xeA[dp], sbo2[dp]);
            x1B[dp] = add2u(xeB[dp], sbo2[dp]);
        }
        const u64* wo = reinterpret_cast<const u64*>(sWoP);
        #pragma unroll
        for (int hp = 0; hp < 4; hp++) {
            float aAx, aAy, aBx, aBy;
            unpack2(aggA[hp], aAx, aAy);
            unpack2(aggB[hp], aBx, aBy);
            float sA[2] = { aAx, aAy }, sB[2] = { aBx, aBy };
            #pragma unroll
            for (int half = 0; half < 2; half++) {
                int h = 2*hp + half;
                u64 aa = dup2(sA[half]), ab = dup2(sB[half]);
                const u64* wr = wo + h*8;
                ulonglong2 w0v = lds2(wr), w1v = lds2(wr+2), w2v = lds2(wr+4);
                u64 w6 = wr[6];
                x1A[0] = fma2u(aa, w0v.x, x1A[0]); x1B[0] = fma2u(ab, w0v.x, x1B[0]);
                x1A[1] = fma2u(aa, w0v.y, x1A[1]); x1B[1] = fma2u(ab, w0v.y, x1B[1]);
                x1A[2] = fma2u(aa, w1v.x, x1A[2]); x1B[2] = fma2u(ab, w1v.x, x1B[2]);
                x1A[3] = fma2u(aa, w1v.y, x1A[3]); x1B[3] = fma2u(ab, w1v.y, x1B[3]);
                x1A[4] = fma2u(aa, w2v.x, x1A[4]); x1B[4] = fma2u(ab, w2v.x, x1B[4]);
                x1A[5] = fma2u(aa, w2v.y, x1A[5]); x1B[5] = fma2u(ab, w2v.y, x1B[5]);
                x1A[6] = fma2u(aa, w6,    x1A[6]); x1B[6] = fma2u(ab, w6,    x1B[6]);
            }
        }
    }

    // ---- series_decomp 1 ----
    const float fc0  = (t < 12) ? (float)(12 - t) : 0.f;
    const float fc29 = (t > 17) ? (float)(t - 17) : 0.f;
    const int hi   = (t + 12 > 29) ? 29 : t + 12;
    const int lom1 = t - 13;
    const int loix = (lom1 < 0) ? 0 : lom1;
    u64 xdA[7], xdB[7];
    #pragma unroll
    for (int dp = 0; dp < 7; dp++) {
        float vx, vy;
        unpack2(x1A[dp], vx, vy);
        xdA[dp] = pack2(decomp25(vx, lane, hi, loix, lom1, fc0, fc29),
                        decomp25(vy, lane, hi, loix, lom1, fc0, fc29));
        unpack2(x1B[dp], vx, vy);
        xdB[dp] = pack2(decomp25(vx, lane, hi, loix, lom1, fc0, fc29),
                        decomp25(vy, lane, hi, loix, lom1, fc0, fc29));
    }

    // ---- FFN: x2 = xd + gelu_exact(xd @ F1) @ F2 (weight LDS shared) ----
    u64 x2A[7], x2B[7];
    {
        u64 yA[7] = {}, yB[7] = {};
        const u64* f1 = reinterpret_cast<const u64*>(sF1P);
        const u64* f2 = reinterpret_cast<const u64*>(sF2P);
        #pragma unroll 5
        for (int f = 0; f < 50; f++) {
            const u64* r1 = f1 + f*8;
            ulonglong2 a0 = lds2(r1), a1 = lds2(r1+2), a2l = lds2(r1+4);
            u64 a6 = r1[6];
            u64 hA = fma2u(xdA[0], a0.x, 0ULL);
            u64 hB = fma2u(xdB[0], a0.x, 0ULL);
            hA = fma2u(xdA[1], a0.y, hA);   hB = fma2u(xdB[1], a0.y, hB);
            hA = fma2u(xdA[2], a1.x, hA);   hB = fma2u(xdB[2], a1.x, hB);
            hA = fma2u(xdA[3], a1.y, hA);   hB = fma2u(xdB[3], a1.y, hB);
            hA = fma2u(xdA[4], a2l.x, hA);  hB = fma2u(xdB[4], a2l.x, hB);
            hA = fma2u(xdA[5], a2l.y, hA);  hB = fma2u(xdB[5], a2l.y, hB);
            hA = fma2u(xdA[6], a6, hA);     hB = fma2u(xdB[6], a6, hB);
            float hx, hy;
            unpack2(hA, hx, hy);
            float hsA = hx + hy;
            unpack2(hB, hx, hy);
            float hsB = hx + hy;
            float gAv = 0.5f * hsA * (1.f + erff(hsA * 0.70710678118654752f));
            float gBv = 0.5f * hsB * (1.f + erff(hsB * 0.70710678118654752f));
            u64 gA2 = dup2(gAv), gB2 = dup2(gBv);
            const u64* r2 = f2 + f*8;
            ulonglong2 b0 = lds2(r2), b1v = lds2(r2+2), b2v = lds2(r2+4);
            u64 b6 = r2[6];
            yA[0] = fma2u(gA2, b0.x, yA[0]);  yB[0] = fma2u(gB2, b0.x, yB[0]);
            yA[1] = fma2u(gA2, b0.y, yA[1]);  yB[1] = fma2u(gB2, b0.y, yB[1]);
            yA[2] = fma2u(gA2, b1v.x, yA[2]); yB[2] = fma2u(gB2, b1v.x, yB[2]);
            yA[3] = fma2u(gA2, b1v.y, yA[3]); yB[3] = fma2u(gB2, b1v.y, yB[3]);
            yA[4] = fma2u(gA2, b2v.x, yA[4]); yB[4] = fma2u(gB2, b2v.x, yB[4]);
            yA[5] = fma2u(gA2, b2v.y, yA[5]); yB[5] = fma2u(gB2, b2v.y, yB[5]);
            yA[6] = fma2u(gA2, b6, yA[6]);    yB[6] = fma2u(gB2, b6, yB[6]);
        }
        #pragma unroll
        for (int dp = 0; dp < 7; dp++) {
            x2A[dp] = add2u(xdA[dp], yA[dp]);
            x2B[dp] = add2u(xdB[dp], yB[dp]);
        }
    }

    // ---- series_decomp 2 + layernorm, per sample ----
    float x3Ax[7], x3Ay[7], x3Bx[7], x3By[7];
    #pragma unroll
    for (int dp = 0; dp < 7; dp++) {
        float vx, vy;
        unpack2(x2A[dp], vx, vy);
        x3Ax[dp] = decomp25(vx, lane, hi, loix, lom1, fc0, fc29);
        x3Ay[dp] = decomp25(vy, lane, hi, loix, lom1, fc0, fc29);
        unpack2(x2B[dp], vx, vy);
        x3Bx[dp] = decomp25(vx, lane, hi, loix, lom1, fc0, fc29);
        x3By[dp] = decomp25(vy, lane, hi, loix, lom1, fc0, fc29);
    }
    {
        float mA = 0.f, mB = 0.f;
        #pragma unroll
        for (int dp = 0; dp < 7; dp++) { mA += x3Ax[dp] + x3Ay[dp]; mB += x3Bx[dp] + x3By[dp]; }
        mA *= (1.f / 14.f); mB *= (1.f / 14.f);
        float vA_ = 0.f, vB_ = 0.f;
        #pragma unroll
        for (int dp = 0; dp < 7; dp++) {
            float dx = x3Ax[dp] - mA, dy = x3Ay[dp] - mA;
            vA_ += dx * dx + dy * dy;
            dx = x3Bx[dp] - mB; dy = x3By[dp] - mB;
            vB_ += dx * dx + dy * dy;
        }
        vA_ *= (1.f / 14.f); vB_ *= (1.f / 14.f);
        float iA = rsqrtf(vA_ + 1e-5f), iB = rsqrtf(vB_ + 1e-5f);
        #pragma unroll
        for (int dp = 0; dp < 7; dp++) {
            float g0 = sg[2*dp], g1 = sg[2*dp+1], b0 = sb[2*dp], b1v = sb[2*dp+1];
            x3Ax[dp] = (x3Ax[dp] - mA) * iA * g0 + b0;
            x3Ay[dp] = (x3Ay[dp] - mA) * iA * g1 + b1v;
            x3Bx[dp] = (x3Bx[dp] - mB) * iB * g0 + b0;
            x3By[dp] = (x3By[dp] - mB) * iB * g1 + b1v;
        }
    }

    // ---- DyConv: stage both samples' x3, accumulate over m (lane = l) ----
    __syncwarp();
    u64* x3sA = scrU;          // 240
    u64* x3sB = scrU + 240;    // 240
    if (act) {
        *reinterpret_cast<ulonglong2*>(x3sA + t*8)     = make_ulonglong2(pack2(x3Ax[0], x3Ay[0]), pack2(x3Ax[1], x3Ay[1]));
        *reinterpret_cast<ulonglong2*>(x3sA + t*8 + 2) = make_ulonglong2(pack2(x3Ax[2], x3Ay[2]), pack2(x3Ax[3], x3Ay[3]));
        *reinterpret_cast<ulonglong2*>(x3sA + t*8 + 4) = make_ulonglong2(pack2(x3Ax[4], x3Ay[4]), pack2(x3Ax[5], x3Ay[5]));
        x3sA[t*8 + 6] = pack2(x3Ax[6], x3Ay[6]);
        *reinterpret_cast<ulonglong2*>(x3sB + t*8)     = make_ulonglong2(pack2(x3Bx[0], x3By[0]), pack2(x3Bx[1], x3By[1]));
        *reinterpret_cast<ulonglong2*>(x3sB + t*8 + 2) = make_ulonglong2(pack2(x3Bx[2], x3By[2]), pack2(x3Bx[3], x3By[3]));
        *reinterpret_cast<ulonglong2*>(x3sB + t*8 + 4) = make_ulonglong2(pack2(x3Bx[4], x3By[4]), pack2(x3Bx[5], x3By[5]));
        x3sB[t*8 + 6] = pack2(x3Bx[6], x3By[6]);
    }
    __syncwarp();
    u64 accA[7], accB[7];
    {
        u64 bias2 = dup2(sbdy[t]);
        #pragma unroll
        for (int dp = 0; dp < 7; dp++) { accA[dp] = bias2; accB[dp] = bias2; }
        #pragma unroll
        for (int m = 0; m < 30; m++) {
            u64 wm2 = dup2(sWdy[m*30 + t]);      // one LDS.32, both samples
            const u64* xa = x3sA + m*8;
            const u64* xb = x3sB + m*8;
            ulonglong2 a0 = lds2(xa), a1 = lds2(xa+2), a2l = lds2(xa+4);
            u64 a6 = xa[6];
            ulonglong2 b0 = lds2(xb), b1v = lds2(xb+2), b2v = lds2(xb+4);
            u64 b6 = xb[6];
            accA[0] = fma2u(a0.x, wm2, accA[0]);  accB[0] = fma2u(b0.x, wm2, accB[0]);
            accA[1] = fma2u(a0.y, wm2, accA[1]);  accB[1] = fma2u(b0.y, wm2, accB[1]);
            accA[2] = fma2u(a1.x, wm2, accA[2]);  accB[2] = fma2u(b1v.x, wm2, accB[2]);
            accA[3] = fma2u(a1.y, wm2, accA[3]);  accB[3] = fma2u(b1v.y, wm2, accB[3]);
            accA[4] = fma2u(a2l.x, wm2, accA[4]); accB[4] = fma2u(b2v.x, wm2, accB[4]);
            accA[5] = fma2u(a2l.y, wm2, accA[5]); accB[5] = fma2u(b2v.y, wm2, accB[5]);
            accA[6] = fma2u(a6,   wm2, accA[6]);  accB[6] = fma2u(b6,   wm2, accB[6]);
        }
    }

    // ---- dy = relu(adj @ h2) -> g_f, both samples (adj LDS shared) ----
    {
        float* foA = g_f + (size_t)smpA * 420;
        float* foB = g_f + (size_t)(smpA+1) * 420;
        const u64* adj = reinterpret_cast<const u64*>(sAdjP);
        #pragma unroll
        for (int i = 0; i < 14; i++) {
            const u64* ar = adj + i*8;
            ulonglong2 a0 = lds2(ar), a1 = lds2(ar+2), a2l = lds2(ar+4);
            u64 a6 = ar[6];
            u64 sA2 = fma2u(a0.x, accA[0], 0ULL);
            u64 sB2 = fma2u(a0.x, accB[0], 0ULL);
            sA2 = fma2u(a0.y, accA[1], sA2);  sB2 = fma2u(a0.y, accB[1], sB2);
            sA2 = fma2u(a1.x, accA[2], sA2);  sB2 = fma2u(a1.x, accB[2], sB2);
            sA2 = fma2u(a1.y, accA[3], sA2);  sB2 = fma2u(a1.y, accB[3], sB2);
            sA2 = fma2u(a2l.x, accA[4], sA2); sB2 = fma2u(a2l.x, accB[4], sB2);
            sA2 = fma2u(a2l.y, accA[5], sA2); sB2 = fma2u(a2l.y, accB[5], sB2);
            sA2 = fma2u(a6, accA[6], sA2);    sB2 = fma2u(a6, accB[6], sB2);
            float ax, ay;
            unpack2(sA2, ax, ay);
            if (act) foA[i*30 + t] = fmaxf(ax + ay, 0.f);
            unpack2(sB2, ax, ay);
            if (act) foB[i*30 + t] = fmaxf(ax + ay, 0.f);
        }
    }
}

// ============================================================================
// Kernel B (tensor): hh = relu(f @ W1 + b1)  M=65536, K=420, N=256  (R8 ver)
// ============================================================================
__global__ __launch_bounds__(256) void kB(const float* __restrict__ W1,
                                          const float* __restrict__ b1)
{
    __shared__ __align__(16) float As[128][36];
    __shared__ __align__(16) float Bs[64][36];
    const int tid = threadIdx.x;
    const int lane = tid & 31, wid = tid >> 5;
    const int wm = wid >> 1, wn = wid & 1;
    const size_t mbase = (size_t)blockIdx.x * 128;
    const int nbase = blockIdx.y * 64;
    float c[2][4][4] = {};

    for (int k0 = 0; k0 < 448; k0 += 32) {
        {
            int m = tid >> 1;
            const float4* gr = reinterpret_cast<const float4*>(g_f + (mbase + m) * 420);
            #pragma unroll
            for (int i = 0; i < 4; i++) {
                int qf = (tid & 1) * 4 + i;
                int kq = (k0 >> 2) + qf;
                float4 vv = (kq < 105) ? gr[kq] : make_float4(0.f,0.f,0.f,0.f);
                *reinterpret_cast<float4*>(&As[m][qf*4]) = vv;
            }
        }
        {
            int kl = tid >> 3;
            int gk = k0 + kl;
            #pragma unroll
            for (int half = 0; half < 2; half++) {
                int n4 = ((tid & 7) + 8*half) * 4;
                float4 vv = make_float4(0.f,0.f,0.f,0.f);
                if (gk < 420)
                    vv = *reinterpret_cast<const float4*>(W1 + (size_t)gk*256 + nbase + n4);
                Bs[n4+0][kl] = vv.x; Bs[n4+1][kl] = vv.y;
                Bs[n4+2][kl] = vv.z; Bs[n4+3][kl] = vv.w;
            }
        }
        __syncthreads();
        #pragma unroll
        for (int ks = 0; ks < 4; ks++) {
            int kk = ks * 8;
            unsigned ah[2][4], al[2][4], bh[4][2], bl[4][2];
            #pragma unroll
            for (int mt = 0; mt < 2; mt++) {
                int r = wm*32 + mt*16 + (lane>>2);
                split_tf32(As[r  ][kk + (lane&3)    ], ah[mt][0], al[mt][0]);
                split_tf32(As[r+8][kk + (lane&3)    ], ah[mt][1], al[mt][1]);
                split_tf32(As[r  ][kk + (lane&3) + 4], ah[mt][2], al[mt][2]);
                split_tf32(As[r+8][kk + (lane&3) + 4], ah[mt][3], al[mt][3]);
            }
            #pragma unroll
            for (int nt = 0; nt < 4; nt++) {
                int nn = wn*32 + nt*8 + (lane>>2);
                split_tf32(Bs[nn][kk + (lane&3)    ], bh[nt][0], bl[nt][0]);
                split_tf32(Bs[nn][kk + (lane&3) + 4], bh[nt][1], bl[nt][1]);
            }
            #pragma unroll
            for (int mt = 0; mt < 2; mt++)
                #pragma unroll
                for (int nt = 0; nt < 4; nt++) {
                    mma_tf32(c[mt][nt], ah[mt], bh[nt]);
                    mma_tf32(c[mt][nt], ah[mt], bl[nt]);
                    mma_tf32(c[mt][nt], al[mt], bh[nt]);
                }
        }
        __syncthreads();
    }
    #pragma unroll
    for (int mt = 0; mt < 2; mt++) {
        int r0 = wm*32 + mt*16 + (lane>>2);
        #pragma unroll
        for (int nt = 0; nt < 4; nt++) {
            int cl = nbase + wn*32 + nt*8 + 2*(lane&3);
            float b0 = b1[cl], b1v = b1[cl+1];
            float2 lo = make_float2(fmaxf(c[mt][nt][0] + b0, 0.f), fmaxf(c[mt][nt][1] + b1v, 0.f));
            float2 hi = make_float2(fmaxf(c[mt][nt][2] + b0, 0.f), fmaxf(c[mt][nt][3] + b1v, 0.f));
            *reinterpret_cast<float2*>(g_hh + (mbase + r0    ) * 256 + cl) = lo;
            *reinterpret_cast<float2*>(g_hh + (mbase + r0 + 8) * 256 + cl) = hi;
        }
    }
}

// ============================================================================
// Kernel C (tensor): hr = [hh|f] @ [W2;Wres] + b2 + bres   (R8 version)
// ============================================================================
__global__ __launch_bounds__(256) void kC(const float* __restrict__ W2,
                                          const float* __restrict__ b2,
                                          const float* __restrict__ Wres,
                                          const float* __restrict__ bres)
{
    __shared__ __align__(16) float As[128][36];
    __shared__ __align__(16) float Bs[64][36];
    const int tid = threadIdx.x;
    const int lane = tid & 31, wid = tid >> 5;
    const int wm = wid >> 1, wn = wid & 1;
    const size_t mbase = (size_t)blockIdx.x * 128;
    float c[2][4][4] = {};

    for (int k0 = 0; k0 < 704; k0 += 32) {
        {
            int m = tid >> 1;
            const float* hrow = g_hh + (mbase + m) * 256;
            const float* frow = g_f  + (mbase + m) * 420;
            #pragma unroll
            for (int i = 0; i < 4; i++) {
                int qf = (tid & 1) * 4 + i;
                int gk = k0 + qf*4;
                float4 vv = make_float4(0.f,0.f,0.f,0.f);
                if (gk < 256) vv = *reinterpret_cast<const float4*>(hrow + gk);
                else { int kf = gk - 256; if (kf < 420) vv = *reinterpret_cast<const float4*>(frow + kf); }
                *reinterpret_cast<float4*>(&As[m][qf*4]) = vv;
            }
        }
        {
            int kl = tid >> 3;
            int gk = k0 + kl;
            #pragma unroll
            for (int half = 0; half < 2; half++) {
                int n4 = ((tid & 7) + 8*half) * 4;
                float4 vv = make_float4(0.f,0.f,0.f,0.f);
                if (gk < 256) vv = *reinterpret_cast<const float4*>(W2 + (size_t)gk*64 + n4);
                else { int kf = gk - 256; if (kf < 420) vv = *reinterpret_cast<const float4*>(Wres + (size_t)kf*64 + n4); }
                Bs[n4+0][kl] = vv.x; Bs[n4+1][kl] = vv.y;
                Bs[n4+2][kl] = vv.z; Bs[n4+3][kl] = vv.w;
            }
        }
        __syncthreads();
        #pragma unroll
        for (int ks = 0; ks < 4; ks++) {
            int kk = ks * 8;
            unsigned ah[2][4], al[2][4], bh[4][2], bl[4][2];
            #pragma unroll
            for (int mt = 0; mt < 2; mt++) {
                int r = wm*32 + mt*16 + (lane>>2);
                split_tf32(As[r  ][kk + (lane&3)    ], ah[mt][0], al[mt][0]);
                split_tf32(As[r+8][kk + (lane&3)    ], ah[mt][1], al[mt][1]);
                split_tf32(As[r  ][kk + (lane&3) + 4], ah[mt][2], al[mt][2]);
                split_tf32(As[r+8][kk + (lane&3) + 4], ah[mt][3], al[mt][3]);
            }
            #pragma unroll
            for (int nt = 0; nt < 4; nt++) {
                int nn = wn*32 + nt*8 + (lane>>2);
                split_tf32(Bs[nn][kk + (lane&3)    ], bh[nt][0], bl[nt][0]);
                split_tf32(Bs[nn][kk + (lane&3) + 4], bh[nt][1], bl[nt][1]);
            }
            #pragma unroll
            for (int mt = 0; mt < 2; mt++)
                #pragma unroll
                for (int nt = 0; nt < 4; nt++) {
                    mma_tf32(c[mt][nt], ah[mt], bh[nt]);
                    mma_tf32(c[mt][nt], ah[mt], bl[nt]);
                    mma_tf32(c[mt][nt], al[mt], bh[nt]);
                }
        }
        __syncthreads();
    }
    #pragma unroll
    for (int mt = 0; mt < 2; mt++) {
        int r0 = wm*32 + mt*16 + (lane>>2);
        #pragma unroll
        for (int nt = 0; nt < 4; nt++) {
            int cl = wn*32 + nt*8 + 2*(lane&3);
            float b0 = b2[cl] + bres[cl], b1v = b2[cl+1] + bres[cl+1];
            float2 lo = make_float2(c[mt][nt][0] + b0, c[mt][nt][1] + b1v);
            float2 hi = make_float2(c[mt][nt][2] + b0, c[mt][nt][3] + b1v);
            *reinterpret_cast<float2*>(g_hr + (mbase + r0    ) * 64 + cl) = lo;
            *reinterpret_cast<float2*>(g_hr + (mbase + r0 + 8) * 64 + cl) = hi;
        }
    }
}

// ============================================================================
// Kernel D: out = LN64(hr) @ W3 + b3   (one warp per sample)  (R8 version)
// ============================================================================
__global__ __launch_bounds__(256) void kD(const float* __restrict__ g_ln,
                                          const float* __restrict__ b_ln,
                                          const float* __restrict__ W3,
                                          const float* __restrict__ b3,
                                          float* __restrict__ out)
{
    int w = threadIdx.x >> 5, lane = threadIdx.x & 31;
    size_t s = (size_t)blockIdx.x * 8 + w;
    const float* r = g_hr + s * 64;
    float v0 = r[lane], v1 = r[lane + 32];
    float sum = v0 + v1, sq = v0 * v0 + v1 * v1;
    #pragma unroll
    for (int o = 16; o; o >>= 1) {
        sum += __shfl_xor_sync(FULL, sum, o);
        sq  += __shfl_xor_sync(FULL, sq,  o);
    }
    float m = sum * (1.f / 64.f);
    float var = sq * (1.f / 64.f) - m * m;
    float inv = rsqrtf(var + 1e-5f);
    float y0 = (v0 - m) * inv * g_ln[lane]      + b_ln[lane];
    float y1 = (v1 - m) * inv * g_ln[lane + 32] + b_ln[lane + 32];
    float d = y0 * W3[lane] + y1 * W3[lane + 32];
    #pragma unroll
    for (int o = 16; o; o >>= 1) d += __shfl_xor_sync(FULL, d, o);
    if (lane == 0) out[s] = d + b3[0];
}

// ============================================================================
extern "C" void kernel_launch(void* const* d_in, const int* in_sizes, int n_in,
                              void* d_out, int out_size)
{
    (void)in_sizes; (void)n_in; (void)out_size;
    const float* x = (const float*)d_in[0];

    kA<<<BATCH / 16, 256>>>(x,
        (const float*)d_in[1],  (const float*)d_in[2],
        (const float*)d_in[3],  (const float*)d_in[4],
        (const float*)d_in[5],  (const float*)d_in[6],
        (const float*)d_in[7],  (const float*)d_in[8],
        (const float*)d_in[9],  (const float*)d_in[10],
        (const float*)d_in[11], (const float*)d_in[12],
        (const float*)d_in[13], (const float*)d_in[14],
        (const float*)d_in[15], (const float*)d_in[16],
        (const float*)d_in[17]);

    kB<<<dim3(BATCH / 128, 4), 256>>>((const float*)d_in[18], (const float*)d_in[19]);

    kC<<<BATCH / 128, 256>>>((const float*)d_in[20], (const float*)d_in[21],
                             (const float*)d_in[22], (const float*)d_in[23]);

    kD<<<BATCH / 8, 256>>>((const float*)d_in[24], (const float*)d_in[25],
                           (const float*)d_in[26], (const float*)d_in[27],
                           (float*)d_out);
}

// round 12
// speedup vs baseline: 1.3590x; 1.1041x over previous
#include <cuda_runtime.h>
#include <math.h>

#define BATCH 65536
#define FULL 0xffffffffu

typedef unsigned long long u64;

// -------- device scratch (allocation-free rule: __device__ globals) --------
__device__ float g_f [(size_t)BATCH * 420];   // DyConv output
__device__ float g_hh[(size_t)BATCH * 256];   // relu(f@W1+b1)

// ---------------- packed f32x2 ops on b64 registers ----------------
__device__ __forceinline__ u64 pack2(float x, float y) {
    u64 r; asm("mov.b64 %0, {%1, %2};" : "=l"(r) : "f"(x), "f"(y)); return r;
}
__device__ __forceinline__ u64 dup2(float s) { return pack2(s, s); }
__device__ __forceinline__ void unpack2(u64 v, float& x, float& y) {
    asm("mov.b64 {%0, %1}, %2;" : "=f"(x), "=f"(y) : "l"(v));
}
__device__ __forceinline__ u64 fma2u(u64 a, u64 b, u64 c) {
    u64 d; asm("fma.rn.f32x2 %0, %1, %2, %3;" : "=l"(d) : "l"(a), "l"(b), "l"(c)); return d;
}
__device__ __forceinline__ u64 add2u(u64 a, u64 b) {
    u64 d; asm("add.rn.f32x2 %0, %1, %2;" : "=l"(d) : "l"(a), "l"(b)); return d;
}
__device__ __forceinline__ ulonglong2 lds2(const u64* p) {
    return *reinterpret_cast<const ulonglong2*>(p);
}

// ---------------- split-bf16 helpers (3xBF16 compensated GEMM) -------------
// e0 -> low half, e1 -> high half (matches mma bf16x2 k-pair layout)
__device__ __forceinline__ void split_bf16x2(float e0, float e1,
                                             unsigned& hi, unsigned& lo) {
    asm("cvt.rn.bf16x2.f32 %0, %1, %2;" : "=r"(hi) : "f"(e1), "f"(e0));
    float h0 = __uint_as_float(hi << 16);
    float h1 = __uint_as_float(hi & 0xffff0000u);
    float r0 = e0 - h0, r1 = e1 - h1;
    asm("cvt.rn.bf16x2.f32 %0, %1, %2;" : "=r"(lo) : "f"(r1), "f"(r0));
}
__device__ __forceinline__ void mma_bf16(float* c, const unsigned* a, const unsigned* b) {
    asm volatile(
        "mma.sync.aligned.m16n8k16.row.col.f32.bf16.bf16.f32 "
        "{%0,%1,%2,%3},{%4,%5,%6,%7},{%8,%9},{%0,%1,%2,%3};"
        : "+f"(c[0]), "+f"(c[1]), "+f"(c[2]), "+f"(c[3])
        : "r"(a[0]), "r"(a[1]), "r"(a[2]), "r"(a[3]), "r"(b[0]), "r"(b[1]));
}

// ---- shuffle-scan series_decomp helper (replicate-pad MA-25) ----
__device__ __forceinline__ float decomp25(float val, int lane, int hi, int loix,
                                          int lom1, float fc0, float fc29) {
    float cs = val;
    #pragma unroll
    for (int off = 1; off < 32; off <<= 1) {
        float o = __shfl_up_sync(FULL, cs, off);
        if (lane >= off) cs += o;
    }
    float cshi = __shfl_sync(FULL, cs, hi);
    float cslo = __shfl_sync(FULL, cs, loix);
    float ssum = cshi - ((lom1 >= 0) ? cslo : 0.f);
    float x0  = __shfl_sync(FULL, val, 0);
    float x29 = __shfl_sync(FULL, val, 29);
    return val - (ssum + fc0 * x0 + fc29 * x29) * (1.f / 25.f);
}

// ---- warp-parallel top-3 with first-index tie-break, then softmax ----
__device__ __forceinline__ void top3softmax(float mv, int lane,
                                            float& w0, float& w1, float& w2,
                                            int& dl0, int& dl1, int& dl2) {
    float wv0, wv1, wv2;
    float mrun = mv;
    #pragma unroll
    for (int p = 0; p < 3; p++) {
        float bv = mrun; int bi = lane;
        #pragma unroll
        for (int off = 16; off; off >>= 1) {
            float vo = __shfl_xor_sync(FULL, bv, off);
            int   io = __shfl_xor_sync(FULL, bi, off);
            if (vo > bv || (vo == bv && io < bi)) { bv = vo; bi = io; }
        }
        if (p == 0) { wv0 = bv; dl0 = bi; }
        else if (p == 1) { wv1 = bv; dl1 = bi; }
        else { wv2 = bv; dl2 = bi; }
        if (lane == bi) mrun = -1e30f;
    }
    float e1 = expf(wv1 - wv0);
    float e2 = expf(wv2 - wv0);
    float inv = 1.f / (1.f + e1 + e2);
    w0 = inv; w1 = e1 * inv; w2 = e2 * inv;
}

// ---- circular correlation for one sample (lane = tau) ----
__device__ __forceinline__ float corr30(const u64* qsU, const u64* ksU,
                                        int t, bool act) {
    u64 acc2[4] = {};
    #pragma unroll
    for (int tq = 0; tq < 30; tq++) {
        int src = tq - t; if (src < 0) src += 30;
        ulonglong2 qa = lds2(qsU + tq*4), qb = lds2(qsU + tq*4 + 2);
        ulonglong2 ka = lds2(ksU + src*4), kb = lds2(ksU + src*4 + 2);
        acc2[0] = fma2u(qa.x, ka.x, acc2[0]);
        acc2[1] = fma2u(qa.y, ka.y, acc2[1]);
        acc2[2] = fma2u(qb.x, kb.x, acc2[2]);
        acc2[3] = fma2u(qb.y, kb.y, acc2[3]);
    }
    u64 s2 = add2u(add2u(acc2[0], acc2[1]), add2u(acc2[2], acc2[3]));
    float sx, sy; unpack2(s2, sx, sy);
    return act ? (sx + sy) * 0.125f : -1e30f;
}

// ============================================================================
// Kernel A: register-resident per-sample pipeline, FFMA2, 2 samples/warp.
// (unchanged from R11 — best measured kA)
// ============================================================================
__global__ __launch_bounds__(256, 2) void kA(
    const float* __restrict__ x,
    const float* __restrict__ W_emb, const float* __restrict__ b_emb,
    const float* __restrict__ Wq, const float* __restrict__ bq,
    const float* __restrict__ Wk, const float* __restrict__ bk,
    const float* __restrict__ Wv, const float* __restrict__ bv,
    const float* __restrict__ Wo, const float* __restrict__ bo,
    const float* __restrict__ Wff1, const float* __restrict__ Wff2,
    const float* __restrict__ gnorm, const float* __restrict__ bnorm,
    const float* __restrict__ Wdy, const float* __restrict__ bdy,
    const float* __restrict__ channels)
{
    __shared__ __align__(16) float2 sWeP[336];
    __shared__ __align__(16) float  sbe[14];
    __shared__ __align__(16) float  sWq[112], sWk[112], sWv[112];
    __shared__ __align__(16) float  sbq[8], sbk[8], sbv[8];
    __shared__ __align__(16) float2 sWoP[64];
    __shared__ __align__(16) float  sbo[14];
    __shared__ __align__(16) float2 sF1P[400];
    __shared__ __align__(16) float2 sF2P[400];
    __shared__ __align__(16) float  sg[14], sb[14];
    __shared__ __align__(16) float  sWdy[900], sbdy[32];
    __shared__ __align__(16) float2 sAdjP[112];
    __shared__ __align__(16) float  scr[8][960];

    const int tid = threadIdx.x;
    for (int i = tid; i < 336; i += 256) {
        int ct = i >> 3, op = i & 7;
        float a = 0.f, b = 0.f;
        if (op < 7) { a = W_emb[(2*op)*42 + ct]; b = W_emb[(2*op+1)*42 + ct]; }
        sWeP[i] = make_float2(a, b);
    }
    for (int i = tid; i < 112; i += 256) { sWq[i]=Wq[i]; sWk[i]=Wk[i]; sWv[i]=Wv[i]; }
    for (int i = tid; i < 64; i += 256) {
        int h = i >> 3, dp = i & 7;
        float a = 0.f, b = 0.f;
        if (dp < 7) { a = Wo[h*14 + 2*dp]; b = Wo[h*14 + 2*dp + 1]; }
        sWoP[i] = make_float2(a, b);
    }
    for (int i = tid; i < 400; i += 256) {
        int f = i >> 3, dp = i & 7;
        float a1 = 0.f, b1v = 0.f, a2 = 0.f, b2v = 0.f;
        if (dp < 7) {
            a1 = Wff1[(2*dp)*50 + f]; b1v = Wff1[(2*dp+1)*50 + f];
            a2 = Wff2[f*14 + 2*dp];   b2v = Wff2[f*14 + 2*dp + 1];
        }
        sF1P[i] = make_float2(a1, b1v);
        sF2P[i] = make_float2(a2, b2v);
    }
    for (int i = tid; i < 900; i += 256) sWdy[i] = Wdy[i];
    if (tid < 30) sbdy[tid] = bdy[tid];
    if (tid < 14) { sbe[tid]=b_emb[tid]; sbo[tid]=bo[tid]; sg[tid]=gnorm[tid]; sb[tid]=bnorm[tid]; }
    if (tid < 8)  { sbq[tid]=bq[tid]; sbk[tid]=bk[tid]; sbv[tid]=bv[tid]; }
    if (tid < 14) {
        const float* row = channels + tid * 14;
        float mx = -1e30f;
        #pragma unroll
        for (int j = 0; j < 14; j++) mx = fmaxf(mx, row[j]);
        float s = 0.f;
        #pragma unroll
        for (int j = 0; j < 14; j++) s += expf(row[j] - mx);
        float inv = 1.f / s;
        #pragma unroll
        for (int j = 0; j < 7; j++)
            sAdjP[tid*8 + j] = make_float2(expf(row[2*j] - mx) * inv,
                                           expf(row[2*j+1] - mx) * inv);
        sAdjP[tid*8 + 7] = make_float2(0.f, 0.f);
    }
    __syncthreads();

    const int w    = tid >> 5;
    const int lane = tid & 31;
    const int t    = (lane < 30) ? lane : 0;
    const bool act = (lane < 30);
    const int smpA = blockIdx.x * 16 + w * 2;
    u64* scrU = reinterpret_cast<u64*>(scr[w]);

    {
        const float4* xpA = reinterpret_cast<const float4*>(x + (size_t)smpA * 420);
        const float4* xpB = reinterpret_cast<const float4*>(x + (size_t)(smpA+1) * 420);
        float4* sp = reinterpret_cast<float4*>(scr[w]);
        #pragma unroll
        for (int i = lane; i < 105; i += 32) { sp[i] = xpA[i]; sp[105 + i] = xpB[i]; }
    }
    __syncwarp();
    float xrA[14], xrB[14];
    #pragma unroll
    for (int d = 0; d < 14; d++) {
        xrA[d] = scr[w][t*14 + d];
        xrB[d] = scr[w][420 + t*14 + d];
    }
    __syncwarp();

    u64 xeA[7], xeB[7];
    {
        const u64* sbe2 = reinterpret_cast<const u64*>(sbe);
        #pragma unroll
        for (int op = 0; op < 7; op++) { xeA[op] = sbe2[op]; xeB[op] = sbe2[op]; }
        const u64* we = reinterpret_cast<const u64*>(sWeP);
        #pragma unroll
        for (int ci = 0; ci < 14; ci++) {
            float upA = __shfl_up_sync(FULL, xrA[ci], 1);
            float dnA = __shfl_down_sync(FULL, xrA[ci], 1);
            float upB = __shfl_up_sync(FULL, xrB[ci], 1);
            float dnB = __shfl_down_sync(FULL, xrB[ci], 1);
            float tapA[3] = { (lane > 0) ? upA : 0.f, xrA[ci], (lane < 29) ? dnA : 0.f };
            float tapB[3] = { (lane > 0) ? upB : 0.f, xrB[ci], (lane < 29) ? dnB : 0.f };
            #pragma unroll
            for (int tp = 0; tp < 3; tp++) {
                u64 xa = dup2(tapA[tp]), xb = dup2(tapB[tp]);
                const u64* wr = we + (ci*3 + tp) * 8;
                ulonglong2 w0 = lds2(wr), w1 = lds2(wr+2), w2 = lds2(wr+4);
                u64 w6 = wr[6];
                xeA[0] = fma2u(xa, w0.x, xeA[0]); xeB[0] = fma2u(xb, w0.x, xeB[0]);
                xeA[1] = fma2u(xa, w0.y, xeA[1]); xeB[1] = fma2u(xb, w0.y, xeB[1]);
                xeA[2] = fma2u(xa, w1.x, xeA[2]); xeB[2] = fma2u(xb, w1.x, xeB[2]);
                xeA[3] = fma2u(xa, w1.y, xeA[3]); xeB[3] = fma2u(xb, w1.y, xeB[3]);
                xeA[4] = fma2u(xa, w2.x, xeA[4]); xeB[4] = fma2u(xb, w2.x, xeB[4]);
                xeA[5] = fma2u(xa, w2.y, xeA[5]); xeB[5] = fma2u(xb, w2.y, xeB[5]);
                xeA[6] = fma2u(xa, w6,   xeA[6]); xeB[6] = fma2u(xb, w6,   xeB[6]);
            }
        }
    }

    u64 qA[4], kA_[4], vA[4], qB[4], kB_[4], vB[4];
    {
        const u64* bq2 = reinterpret_cast<const u64*>(sbq);
        const u64* bk2 = reinterpret_cast<const u64*>(sbk);
        const u64* bv2 = reinterpret_cast<const u64*>(sbv);
        #pragma unroll
        for (int hp = 0; hp < 4; hp++) {
            qA[hp]=bq2[hp]; kA_[hp]=bk2[hp]; vA[hp]=bv2[hp];
            qB[hp]=bq2[hp]; kB_[hp]=bk2[hp]; vB[hp]=bv2[hp];
        }
        const u64* wq2 = reinterpret_cast<const u64*>(sWq);
        const u64* wk2 = reinterpret_cast<const u64*>(sWk);
        const u64* wv2 = reinterpret_cast<const u64*>(sWv);
        #pragma unroll
        for (int dp = 0; dp < 7; dp++) {
            float ax, ay, bx, by;
            unpack2(xeA[dp], ax, ay);
            unpack2(xeB[dp], bx, by);
            float sA[2] = { ax, ay }, sB[2] = { bx, by };
            #pragma unroll
            for (int half = 0; half < 2; half++) {
                int d = 2*dp + half;
                u64 xa = dup2(sA[half]), xb = dup2(sB[half]);
                ulonglong2 qa = lds2(wq2 + d*4), qb = lds2(wq2 + d*4 + 2);
                ulonglong2 ka = lds2(wk2 + d*4), kb = lds2(wk2 + d*4 + 2);
                ulonglong2 va = lds2(wv2 + d*4), vb = lds2(wv2 + d*4 + 2);
                qA[0] = fma2u(xa, qa.x, qA[0]); qB[0] = fma2u(xb, qa.x, qB[0]);
                qA[1] = fma2u(xa, qa.y, qA[1]); qB[1] = fma2u(xb, qa.y, qB[1]);
                qA[2] = fma2u(xa, qb.x, qA[2]); qB[2] = fma2u(xb, qb.x, qB[2]);
                qA[3] = fma2u(xa, qb.y, qA[3]); qB[3] = fma2u(xb, qb.y, qB[3]);
                kA_[0] = fma2u(xa, ka.x, kA_[0]); kB_[0] = fma2u(xb, ka.x, kB_[0]);
                kA_[1] = fma2u(xa, ka.y, kA_[1]); kB_[1] = fma2u(xb, ka.y, kB_[1]);
                kA_[2] = fma2u(xa, kb.x, kA_[2]); kB_[2] = fma2u(xb, kb.x, kB_[2]);
                kA_[3] = fma2u(xa, kb.y, kA_[3]); kB_[3] = fma2u(xb, kb.y, kB_[3]);
                vA[0] = fma2u(xa, va.x, vA[0]); vB[0] = fma2u(xb, va.x, vB[0]);
                vA[1] = fma2u(xa, va.y, vA[1]); vB[1] = fma2u(xb, va.y, vB[1]);
                vA[2] = fma2u(xa, vb.x, vA[2]); vB[2] = fma2u(xb, vb.x, vB[2]);
                vA[3] = fma2u(xa, vb.y, vA[3]); vB[3] = fma2u(xb, vb.y, vB[3]);
            }
        }
    }

    u64* qsA = scrU;
    u64* ksA = scrU + 120;
    u64* qsB = scrU + 240;
    u64* ksB = scrU + 360;
    if (act) {
        *reinterpret_cast<ulonglong2*>(qsA + t*4)     = make_ulonglong2(qA[0], qA[1]);
        *reinterpret_cast<ulonglong2*>(qsA + t*4 + 2) = make_ulonglong2(qA[2], qA[3]);
        *reinterpret_cast<ulonglong2*>(ksA + t*4)     = make_ulonglong2(kA_[0], kA_[1]);
        *reinterpret_cast<ulonglong2*>(ksA + t*4 + 2) = make_ulonglong2(kA_[2], kA_[3]);
        *reinterpret_cast<ulonglong2*>(qsB + t*4)     = make_ulonglong2(qB[0], qB[1]);
        *reinterpret_cast<ulonglong2*>(qsB + t*4 + 2) = make_ulonglong2(qB[2], qB[3]);
        *reinterpret_cast<ulonglong2*>(ksB + t*4)     = make_ulonglong2(kB_[0], kB_[1]);
        *reinterpret_cast<ulonglong2*>(ksB + t*4 + 2) = make_ulonglong2(kB_[2], kB_[3]);
    }
    __syncwarp();

    float mvA = corr30(qsA, ksA, t, act);
    float mvB = corr30(qsB, ksB, t, act);
    float w0A, w1A, w2A, w0B, w1B, w2B;
    int dl0A, dl1A, dl2A, dl0B, dl1B, dl2B;
    top3softmax(mvA, lane, w0A, w1A, w2A, dl0A, dl1A, dl2A);
    top3softmax(mvB, lane, w0B, w1B, w2B, dl0B, dl1B, dl2B);

    u64 aggA[4], aggB[4];
    {
        int s0 = t + dl0A; if (s0 >= 30) s0 -= 30;
        int s1 = t + dl1A; if (s1 >= 30) s1 -= 30;
        int s2 = t + dl2A; if (s2 >= 30) s2 -= 30;
        u64 c0 = dup2(w0A), c1 = dup2(w1A), c2 = dup2(w2A);
        #pragma unroll
        for (int hp = 0; hp < 4; hp++) {
            u64 y0 = __shfl_sync(FULL, vA[hp], s0);
            u64 y1 = __shfl_sync(FULL, vA[hp], s1);
            u64 y2 = __shfl_sync(FULL, vA[hp], s2);
            aggA[hp] = fma2u(c0, y0, fma2u(c1, y1, fma2u(c2, y2, 0ULL)));
        }
    }
    {
        int s0 = t + dl0B; if (s0 >= 30) s0 -= 30;
        int s1 = t + dl1B; if (s1 >= 30) s1 -= 30;
        int s2 = t + dl2B; if (s2 >= 30) s2 -= 30;
        u64 c0 = dup2(w0B), c1 = dup2(w1B), c2 = dup2(w2B);
        #pragma unroll
        for (int hp = 0; hp < 4; hp++) {
            u64 y0 = __shfl_sync(FULL, vB[hp], s0);
            u64 y1 = __shfl_sync(FULL, vB[hp], s1);
            u64 y2 = __shfl_sync(FULL, vB[hp], s2);
            aggB[hp] = fma2u(c0, y0, fma2u(c1, y1, fma2u(c2, y2, 0ULL)));
        }
    }

    u64 x1A[7], x1B[7];
    {
        const u64* sbo2 = reinterpret_cast<const u64*>(sbo);
        #pragma unroll
        for (int dp = 0; dp < 7; dp++) {
            x1A[dp] = add2u(xeA[dp], sbo2[dp]);
            x1B[dp] = add2u(xeB[dp], sbo2[dp]);
        }
        const u64* wo = reinterpret_cast<const u64*>(sWoP);
        #pragma unroll
        for (int hp = 0; hp < 4; hp++) {
            float aAx, aAy, aBx, aBy;
            unpack2(aggA[hp], aAx, aAy);
            unpack2(aggB[hp], aBx, aBy);
            float sA[2] = { aAx, aAy }, sB[2] = { aBx, aBy };
            #pragma unroll
            for (int half = 0; half < 2; half++) {
                int h = 2*hp + half;
                u64 aa = dup2(sA[half]), ab = dup2(sB[half]);
                const u64* wr = wo + h*8;
                ulonglong2 w0v = lds2(wr), w1v = lds2(wr+2), w2v = lds2(wr+4);
                u64 w6 = wr[6];
                x1A[0] = fma2u(aa, w0v.x, x1A[0]); x1B[0] = fma2u(ab, w0v.x, x1B[0]);
                x1A[1] = fma2u(aa, w0v.y, x1A[1]); x1B[1] = fma2u(ab, w0v.y, x1B[1]);
                x1A[2] = fma2u(aa, w1v.x, x1A[2]); x1B[2] = fma2u(ab, w1v.x, x1B[2]);
                x1A[3] = fma2u(aa, w1v.y, x1A[3]); x1B[3] = fma2u(ab, w1v.y, x1B[3]);
                x1A[4] = fma2u(aa, w2v.x, x1A[4]); x1B[4] = fma2u(ab, w2v.x, x1B[4]);
                x1A[5] = fma2u(aa, w2v.y, x1A[5]); x1B[5] = fma2u(ab, w2v.y, x1B[5]);
                x1A[6] = fma2u(aa, w6,    x1A[6]); x1B[6] = fma2u(ab, w6,    x1B[6]);
            }
        }
    }

    const float fc0  = (t < 12) ? (float)(12 - t) : 0.f;
    const float fc29 = (t > 17) ? (float)(t - 17) : 0.f;
    const int hi   = (t + 12 > 29) ? 29 : t + 12;
    const int lom1 = t - 13;
    const int loix = (lom1 < 0) ? 0 : lom1;
    u64 xdA[7], xdB[7];
    #pragma unroll
    for (int dp = 0; dp < 7; dp++) {
        float vx, vy;
        unpack2(x1A[dp], vx, vy);
        xdA[dp] = pack2(decomp25(vx, lane, hi, loix, lom1, fc0, fc29),
                        decomp25(vy, lane, hi, loix, lom1, fc0, fc29));
        unpack2(x1B[dp], vx, vy);
        xdB[dp] = pack2(decomp25(vx, lane, hi, loix, lom1, fc0, fc29),
                        decomp25(vy, lane, hi, loix, lom1, fc0, fc29));
    }

    u64 x2A[7], x2B[7];
    {
        u64 yA[7] = {}, yB[7] = {};
        const u64* f1 = reinterpret_cast<const u64*>(sF1P);
        const u64* f2 = reinterpret_cast<const u64*>(sF2P);
        #pragma unroll 5
        for (int f = 0; f < 50; f++) {
            const u64* r1 = f1 + f*8;
            ulonglong2 a0 = lds2(r1), a1 = lds2(r1+2), a2l = lds2(r1+4);
            u64 a6 = r1[6];
            u64 hA = fma2u(xdA[0], a0.x, 0ULL);
            u64 hB = fma2u(xdB[0], a0.x, 0ULL);
            hA = fma2u(xdA[1], a0.y, hA);   hB = fma2u(xdB[1], a0.y, hB);
            hA = fma2u(xdA[2], a1.x, hA);   hB = fma2u(xdB[2], a1.x, hB);
            hA = fma2u(xdA[3], a1.y, hA);   hB = fma2u(xdB[3], a1.y, hB);
            hA = fma2u(xdA[4], a2l.x, hA);  hB = fma2u(xdB[4], a2l.x, hB);
            hA = fma2u(xdA[5], a2l.y, hA);  hB = fma2u(xdB[5], a2l.y, hB);
            hA = fma2u(xdA[6], a6, hA);     hB = fma2u(xdB[6], a6, hB);
            float hx, hy;
            unpack2(hA, hx, hy);
            float hsA = hx + hy;
            unpack2(hB, hx, hy);
            float hsB = hx + hy;
            float gAv = 0.5f * hsA * (1.f + erff(hsA * 0.70710678118654752f));
            float gBv = 0.5f * hsB * (1.f + erff(hsB * 0.70710678118654752f));
            u64 gA2 = dup2(gAv), gB2 = dup2(gBv);
            const u64* r2 = f2 + f*8;
            ulonglong2 b0 = lds2(r2), b1v = lds2(r2+2), b2v = lds2(r2+4);
            u64 b6 = r2[6];
            yA[0] = fma2u(gA2, b0.x, yA[0]);  yB[0] = fma2u(gB2, b0.x, yB[0]);
            yA[1] = fma2u(gA2, b0.y, yA[1]);  yB[1] = fma2u(gB2, b0.y, yB[1]);
            yA[2] = fma2u(gA2, b1v.x, yA[2]); yB[2] = fma2u(gB2, b1v.x, yB[2]);
            yA[3] = fma2u(gA2, b1v.y, yA[3]); yB[3] = fma2u(gB2, b1v.y, yB[3]);
            yA[4] = fma2u(gA2, b2v.x, yA[4]); yB[4] = fma2u(gB2, b2v.x, yB[4]);
            yA[5] = fma2u(gA2, b2v.y, yA[5]); yB[5] = fma2u(gB2, b2v.y, yB[5]);
            yA[6] = fma2u(gA2, b6, yA[6]);    yB[6] = fma2u(gB2, b6, yB[6]);
        }
        #pragma unroll
        for (int dp = 0; dp < 7; dp++) {
            x2A[dp] = add2u(xdA[dp], yA[dp]);
            x2B[dp] = add2u(xdB[dp], yB[dp]);
        }
    }

    float x3Ax[7], x3Ay[7], x3Bx[7], x3By[7];
    #pragma unroll
    for (int dp = 0; dp < 7; dp++) {
        float vx, vy;
        unpack2(x2A[dp], vx, vy);
        x3Ax[dp] = decomp25(vx, lane, hi, loix, lom1, fc0, fc29);
        x3Ay[dp] = decomp25(vy, lane, hi, loix, lom1, fc0, fc29);
        unpack2(x2B[dp], vx, vy);
        x3Bx[dp] = decomp25(vx, lane, hi, loix, lom1, fc0, fc29);
        x3By[dp] = decomp25(vy, lane, hi, loix, lom1, fc0, fc29);
    }
    {
        float mA = 0.f, mB = 0.f;
        #pragma unroll
        for (int dp = 0; dp < 7; dp++) { mA += x3Ax[dp] + x3Ay[dp]; mB += x3Bx[dp] + x3By[dp]; }
        mA *= (1.f / 14.f); mB *= (1.f / 14.f);
        float vA_ = 0.f, vB_ = 0.f;
        #pragma unroll
        for (int dp = 0; dp < 7; dp++) {
            float dx = x3Ax[dp] - mA, dy = x3Ay[dp] - mA;
            vA_ += dx * dx + dy * dy;
            dx = x3Bx[dp] - mB; dy = x3By[dp] - mB;
            vB_ += dx * dx + dy * dy;
        }
        vA_ *= (1.f / 14.f); vB_ *= (1.f / 14.f);
        float iA = rsqrtf(vA_ + 1e-5f), iB = rsqrtf(vB_ + 1e-5f);
        #pragma unroll
        for (int dp = 0; dp < 7; dp++) {
            float g0 = sg[2*dp], g1 = sg[2*dp+1], b0 = sb[2*dp], b1v = sb[2*dp+1];
            x3Ax[dp] = (x3Ax[dp] - mA) * iA * g0 + b0;
            x3Ay[dp] = (x3Ay[dp] - mA) * iA * g1 + b1v;
            x3Bx[dp] = (x3Bx[dp] - mB) * iB * g0 + b0;
            x3By[dp] = (x3By[dp] - mB) * iB * g1 + b1v;
        }
    }

    __syncwarp();
    u64* x3sA = scrU;
    u64* x3sB = scrU + 240;
    if (act) {
        *reinterpret_cast<ulonglong2*>(x3sA + t*8)     = make_ulonglong2(pack2(x3Ax[0], x3Ay[0]), pack2(x3Ax[1], x3Ay[1]));
        *reinterpret_cast<ulonglong2*>(x3sA + t*8 + 2) = make_ulonglong2(pack2(x3Ax[2], x3Ay[2]), pack2(x3Ax[3], x3Ay[3]));
        *reinterpret_cast<ulonglong2*>(x3sA + t*8 + 4) = make_ulonglong2(pack2(x3Ax[4], x3Ay[4]), pack2(x3Ax[5], x3Ay[5]));
        x3sA[t*8 + 6] = pack2(x3Ax[6], x3Ay[6]);
        *reinterpret_cast<ulonglong2*>(x3sB + t*8)     = make_ulonglong2(pack2(x3Bx[0], x3By[0]), pack2(x3Bx[1], x3By[1]));
        *reinterpret_cast<ulonglong2*>(x3sB + t*8 + 2) = make_ulonglong2(pack2(x3Bx[2], x3By[2]), pack2(x3Bx[3], x3By[3]));
        *reinterpret_cast<ulonglong2*>(x3sB + t*8 + 4) = make_ulonglong2(pack2(x3Bx[4], x3By[4]), pack2(x3Bx[5], x3By[5]));
        x3sB[t*8 + 6] = pack2(x3Bx[6], x3By[6]);
    }
    __syncwarp();
    u64 accA[7], accB[7];
    {
        u64 bias2 = dup2(sbdy[t]);
        #pragma unroll
        for (int dp = 0; dp < 7; dp++) { accA[dp] = bias2; accB[dp] = bias2; }
        #pragma unroll
        for (int m = 0; m < 30; m++) {
            u64 wm2 = dup2(sWdy[m*30 + t]);
            const u64* xa = x3sA + m*8;
            const u64* xb = x3sB + m*8;
            ulonglong2 a0 = lds2(xa), a1 = lds2(xa+2), a2l = lds2(xa+4);
            u64 a6 = xa[6];
            ulonglong2 b0 = lds2(xb), b1v = lds2(xb+2), b2v = lds2(xb+4);
            u64 b6 = xb[6];
            accA[0] = fma2u(a0.x, wm2, accA[0]);  accB[0] = fma2u(b0.x, wm2, accB[0]);
            accA[1] = fma2u(a0.y, wm2, accA[1]);  accB[1] = fma2u(b0.y, wm2, accB[1]);
            accA[2] = fma2u(a1.x, wm2, accA[2]);  accB[2] = fma2u(b1v.x, wm2, accB[2]);
            accA[3] = fma2u(a1.y, wm2, accA[3]);  accB[3] = fma2u(b1v.y, wm2, accB[3]);
            accA[4] = fma2u(a2l.x, wm2, accA[4]); accB[4] = fma2u(b2v.x, wm2, accB[4]);
            accA[5] = fma2u(a2l.y, wm2, accA[5]); accB[5] = fma2u(b2v.y, wm2, accB[5]);
            accA[6] = fma2u(a6,   wm2, accA[6]);  accB[6] = fma2u(b6,   wm2, accB[6]);
        }
    }

    {
        float* foA = g_f + (size_t)smpA * 420;
        float* foB = g_f + (size_t)(smpA+1) * 420;
        const u64* adj = reinterpret_cast<const u64*>(sAdjP);
        #pragma unroll
        for (int i = 0; i < 14; i++) {
            const u64* ar = adj + i*8;
            ulonglong2 a0 = lds2(ar), a1 = lds2(ar+2), a2l = lds2(ar+4);
            u64 a6 = ar[6];
            u64 sA2 = fma2u(a0.x, accA[0], 0ULL);
            u64 sB2 = fma2u(a0.x, accB[0], 0ULL);
            sA2 = fma2u(a0.y, accA[1], sA2);  sB2 = fma2u(a0.y, accB[1], sB2);
            sA2 = fma2u(a1.x, accA[2], sA2);  sB2 = fma2u(a1.x, accB[2], sB2);
            sA2 = fma2u(a1.y, accA[3], sA2);  sB2 = fma2u(a1.y, accB[3], sB2);
            sA2 = fma2u(a2l.x, accA[4], sA2); sB2 = fma2u(a2l.x, accB[4], sB2);
            sA2 = fma2u(a2l.y, accA[5], sA2); sB2 = fma2u(a2l.y, accB[5], sB2);
            sA2 = fma2u(a6, accA[6], sA2);    sB2 = fma2u(a6, accB[6], sB2);
            float ax, ay;
            unpack2(sA2, ax, ay);
            if (act) foA[i*30 + t] = fmaxf(ax + ay, 0.f);
            unpack2(sB2, ax, ay);
            if (act) foB[i*30 + t] = fmaxf(ax + ay, 0.f);
        }
    }
}

// ============================================================================
// Kernel B (3xBF16 m16n8k16, pre-split at staging): hh = relu(f @ W1 + b1)
// M=65536, K=420 (pad 448), N=256. BM=128, BN=64 (grid.y=4), BK=32.
// ============================================================================
__global__ __launch_bounds__(256) void kB(const float* __restrict__ W1,
                                          const float* __restrict__ b1)
{
    __shared__ unsigned Ah[128][20], Al[128][20];   // [m][kp], kp = k/2 (16 used)
    __shared__ unsigned Bh[64][20],  Bl[64][20];    // [n][kp]
    const int tid = threadIdx.x;
    const int lane = tid & 31, wid = tid >> 5;
    const int wm = wid >> 1, wn = wid & 1;
    const int c4 = lane & 3;
    const size_t mbase = (size_t)blockIdx.x * 128;
    const int nbase = blockIdx.y * 64;
    float c[2][4][4] = {};

    for (int k0 = 0; k0 < 448; k0 += 32) {
        // A stage: row m = tid>>1, half = tid&1 covers kps [half*8, half*8+8)
        {
            int m = tid >> 1, half = tid & 1;
            const float4* gr = reinterpret_cast<const float4*>(g_f + (mbase + m) * 420);
            #pragma unroll
            for (int j = 0; j < 4; j++) {
                int kq = (k0 >> 2) + half*4 + j;
                float4 vv = (kq < 105) ? gr[kq] : make_float4(0.f,0.f,0.f,0.f);
                int kp = half*8 + 2*j;
                unsigned h, l;
                split_bf16x2(vv.x, vv.y, h, l); Ah[m][kp]   = h; Al[m][kp]   = l;
                split_bf16x2(vv.z, vv.w, h, l); Ah[m][kp+1] = h; Al[m][kp+1] = l;
            }
        }
        // B stage: thread -> (kp = tid>>4, n4 = (tid&15)*4); loads k rows 2kp, 2kp+1
        {
            int kp = tid >> 4;
            int n4 = (tid & 15) * 4;
            int gk0 = k0 + 2*kp, gk1 = gk0 + 1;
            float4 r0 = (gk0 < 420) ? *reinterpret_cast<const float4*>(W1 + (size_t)gk0*256 + nbase + n4)
                                    : make_float4(0.f,0.f,0.f,0.f);
            float4 r1 = (gk1 < 420) ? *reinterpret_cast<const float4*>(W1 + (size_t)gk1*256 + nbase + n4)
                                    : make_float4(0.f,0.f,0.f,0.f);
            unsigned h, l;
            split_bf16x2(r0.x, r1.x, h, l); Bh[n4+0][kp] = h; Bl[n4+0][kp] = l;
            split_bf16x2(r0.y, r1.y, h, l); Bh[n4+1][kp] = h; Bl[n4+1][kp] = l;
            split_bf16x2(r0.z, r1.z, h, l); Bh[n4+2][kp] = h; Bl[n4+2][kp] = l;
            split_bf16x2(r0.w, r1.w, h, l); Bh[n4+3][kp] = h; Bl[n4+3][kp] = l;
        }
        __syncthreads();
        #pragma unroll
        for (int ks = 0; ks < 2; ks++) {
            int kb = ks * 8;
            unsigned ah[2][4], al[2][4], bh[4][2], bl[4][2];
            #pragma unroll
            for (int mt = 0; mt < 2; mt++) {
                int r = wm*32 + mt*16 + (lane>>2);
                ah[mt][0] = Ah[r  ][kb + c4];     al[mt][0] = Al[r  ][kb + c4];
                ah[mt][1] = Ah[r+8][kb + c4];     al[mt][1] = Al[r+8][kb + c4];
                ah[mt][2] = Ah[r  ][kb + c4 + 4]; al[mt][2] = Al[r  ][kb + c4 + 4];
                ah[mt][3] = Ah[r+8][kb + c4 + 4]; al[mt][3] = Al[r+8][kb + c4 + 4];
            }
            #pragma unroll
            for (int nt = 0; nt < 4; nt++) {
                int nn = wn*32 + nt*8 + (lane>>2);
                bh[nt][0] = Bh[nn][kb + c4];     bl[nt][0] = Bl[nn][kb + c4];
                bh[nt][1] = Bh[nn][kb + c4 + 4]; bl[nt][1] = Bl[nn][kb + c4 + 4];
            }
            #pragma unroll
            for (int mt = 0; mt < 2; mt++)
                #pragma unroll
                for (int nt = 0; nt < 4; nt++) {
                    mma_bf16(c[mt][nt], ah[mt], bh[nt]);
                    mma_bf16(c[mt][nt], ah[mt], bl[nt]);
                    mma_bf16(c[mt][nt], al[mt], bh[nt]);
                }
        }
        __syncthreads();
    }
    #pragma unroll
    for (int mt = 0; mt < 2; mt++) {
        int r0 = wm*32 + mt*16 + (lane>>2);
        #pragma unroll
        for (int nt = 0; nt < 4; nt++) {
            int cl = nbase + wn*32 + nt*8 + 2*(lane&3);
            float b0 = b1[cl], b1v = b1[cl+1];
            float2 lo = make_float2(fmaxf(c[mt][nt][0] + b0, 0.f), fmaxf(c[mt][nt][1] + b1v, 0.f));
            float2 hi = make_float2(fmaxf(c[mt][nt][2] + b0, 0.f), fmaxf(c[mt][nt][3] + b1v, 0.f));
            *reinterpret_cast<float2*>(g_hh + (mbase + r0    ) * 256 + cl) = lo;
            *reinterpret_cast<float2*>(g_hh + (mbase + r0 + 8) * 256 + cl) = hi;
        }
    }
}

// ============================================================================
// Kernel C (3xBF16, fused LN head): hr = [hh|f]@[W2;Wres]+b2+bres, then
// out = LN64(hr) @ W3 + b3 from register fragments. K=676 (pad 704), BK=32.
// ============================================================================
__global__ __launch_bounds__(256) void kC(const float* __restrict__ W2,
                                          const float* __restrict__ b2,
                                          const float* __restrict__ Wres,
                                          const float* __restrict__ bres,
                                          const float* __restrict__ g_ln,
                                          const float* __restrict__ b_ln,
                                          const float* __restrict__ W3,
                                          const float* __restrict__ b3,
                                          float* __restrict__ out)
{
    __shared__ unsigned Ah[128][20], Al[128][20];
    __shared__ unsigned Bh[64][20],  Bl[64][20];
    __shared__ float sbb[64];        // b2+bres
    __shared__ float sgw[64];        // g_ln*W3
    __shared__ float sp[128][2][3];  // per-row half partials (sv, sq, sg)
    __shared__ float sconst[2];      // G, cb
    const int tid = threadIdx.x;
    const int lane = tid & 31, wid = tid >> 5;
    const int wm = wid >> 1, wn = wid & 1;
    const int c4 = lane & 3;
    const size_t mbase = (size_t)blockIdx.x * 128;
    float c[2][4][4] = {};

    if (tid < 64) {
        sbb[tid] = b2[tid] + bres[tid];
        sgw[tid] = g_ln[tid] * W3[tid];
    }

    for (int k0 = 0; k0 < 704; k0 += 32) {
        // A stage: concat [hh(256) | f(420)]
        {
            int m = tid >> 1, half = tid & 1;
            const float* hrow = g_hh + (mbase + m) * 256;
            const float* frow = g_f  + (mbase + m) * 420;
            #pragma unroll
            for (int j = 0; j < 4; j++) {
                int gk = k0 + half*16 + 4*j;
                float4 vv = make_float4(0.f,0.f,0.f,0.f);
                if (gk < 256) vv = *reinterpret_cast<const float4*>(hrow + gk);
                else { int kf = gk - 256; if (kf < 420) vv = *reinterpret_cast<const float4*>(frow + kf); }
                int kp = half*8 + 2*j;
                unsigned h, l;
                split_bf16x2(vv.x, vv.y, h, l); Ah[m][kp]   = h; Al[m][kp]   = l;
                split_bf16x2(vv.z, vv.w, h, l); Ah[m][kp+1] = h; Al[m][kp+1] = l;
            }
        }
        // B stage: concat [W2(256x64) ; Wres(420x64)]
        {
            int kp = tid >> 4;
            int n4 = (tid & 15) * 4;
            int gk0 = k0 + 2*kp, gk1 = gk0 + 1;
            float4 r0 = make_float4(0.f,0.f,0.f,0.f);
            float4 r1 = make_float4(0.f,0.f,0.f,0.f);
            if (gk0 < 256) r0 = *reinterpret_cast<const float4*>(W2 + (size_t)gk0*64 + n4);
            else { int kf = gk0 - 256; if (kf < 420) r0 = *reinterpret_cast<const float4*>(Wres + (size_t)kf*64 + n4); }
            if (gk1 < 256) r1 = *reinterpret_cast<const float4*>(W2 + (size_t)gk1*64 + n4);
            else { int kf = gk1 - 256; if (kf < 420) r1 = *reinterpret_cast<const float4*>(Wres + (size_t)kf*64 + n4); }
            unsigned h, l;
            split_bf16x2(r0.x, r1.x, h, l); Bh[n4+0][kp] = h; Bl[n4+0][kp] = l;
            split_bf16x2(r0.y, r1.y, h, l); Bh[n4+1][kp] = h; Bl[n4+1][kp] = l;
            split_bf16x2(r0.z, r1.z, h, l); Bh[n4+2][kp] = h; Bl[n4+2][kp] = l;
            split_bf16x2(r0.w, r1.w, h, l); Bh[n4+3][kp] = h; Bl[n4+3][kp] = l;
        }
        __syncthreads();
        #pragma unroll
        for (int ks = 0; ks < 2; ks++) {
            int kb = ks * 8;
            unsigned ah[2][4], al[2][4], bh[4][2], bl[4][2];
            #pragma unroll
            for (int mt = 0; mt < 2; mt++) {
                int r = wm*32 + mt*16 + (lane>>2);
                ah[mt][0] = Ah[r  ][kb + c4];     al[mt][0] = Al[r  ][kb + c4];
                ah[mt][1] = Ah[r+8][kb + c4];     al[mt][1] = Al[r+8][kb + c4];
                ah[mt][2] = Ah[r  ][kb + c4 + 4]; al[mt][2] = Al[r  ][kb + c4 + 4];
                ah[mt][3] = Ah[r+8][kb + c4 + 4]; al[mt][3] = Al[r+8][kb + c4 + 4];
            }
            #pragma unroll
            for (int nt = 0; nt < 4; nt++) {
                int nn = wn*32 + nt*8 + (lane>>2);
                bh[nt][0] = Bh[nn][kb + c4];     bl[nt][0] = Bl[nn][kb + c4];
                bh[nt][1] = Bh[nn][kb + c4 + 4]; bl[nt][1] = Bl[nn][kb + c4 + 4];
            }
            #pragma unroll
            for (int mt = 0; mt < 2; mt++)
                #pragma unroll
                for (int nt = 0; nt < 4; nt++) {
                    mma_bf16(c[mt][nt], ah[mt], bh[nt]);
                    mma_bf16(c[mt][nt], ah[mt], bl[nt]);
                    mma_bf16(c[mt][nt], al[mt], bh[nt]);
                }
        }
        __syncthreads();
    }

    // ---- fused epilogue: partial LN sums per (row, wn-half) ----
    #pragma unroll
    for (int mt = 0; mt < 2; mt++) {
        #pragma unroll
        for (int rb = 0; rb < 2; rb++) {
            float sv = 0.f, sq = 0.f, sgd = 0.f;
            #pragma unroll
            for (int nt = 0; nt < 4; nt++) {
                int cl = wn*32 + nt*8 + 2*(lane&3);
                float v0 = c[mt][nt][2*rb]     + sbb[cl];
                float v1 = c[mt][nt][2*rb + 1] + sbb[cl+1];
                sv += v0 + v1;
                sq += v0*v0 + v1*v1;
                sgd += v0*sgw[cl] + v1*sgw[cl+1];
            }
            sv += __shfl_xor_sync(FULL, sv, 1);
            sq += __shfl_xor_sync(FULL, sq, 1);
            sgd += __shfl_xor_sync(FULL, sgd, 1);
            sv += __shfl_xor_sync(FULL, sv, 2);
            sq += __shfl_xor_sync(FULL, sq, 2);
            sgd += __shfl_xor_sync(FULL, sgd, 2);
            if ((lane & 3) == 0) {
                int row = wm*32 + mt*16 + rb*8 + (lane>>2);
                sp[row][wn][0] = sv;
                sp[row][wn][1] = sq;
                sp[row][wn][2] = sgd;
            }
        }
    }
    if (tid == 0) {
        float G = 0.f, cb = b3[0];
        for (int d = 0; d < 64; d++) { G += sgw[d]; cb += b_ln[d] * W3[d]; }
        sconst[0] = G; sconst[1] = cb;
    }
    __syncthreads();
    if (tid < 128) {
        int row = tid;
        float sv  = sp[row][0][0] + sp[row][1][0];
        float sq  = sp[row][0][1] + sp[row][1][1];
        float sgd = sp[row][0][2] + sp[row][1][2];
        float m = sv * (1.f / 64.f);
        float var = sq * (1.f / 64.f) - m * m;
        float invs = rsqrtf(var + 1e-5f);
        out[mbase + row] = invs * (sgd - m * sconst[0]) + sconst[1];
    }
}

// ============================================================================
extern "C" void kernel_launch(void* const* d_in, const int* in_sizes, int n_in,
                              void* d_out, int out_size)
{
    (void)in_sizes; (void)n_in; (void)out_size;
    const float* x = (const float*)d_in[0];

    kA<<<BATCH / 16, 256>>>(x,
        (const float*)d_in[1],  (const float*)d_in[2],
        (const float*)d_in[3],  (const float*)d_in[4],
        (const float*)d_in[5],  (const float*)d_in[6],
        (const float*)d_in[7],  (const float*)d_in[8],
        (const float*)d_in[9],  (const float*)d_in[10],
        (const float*)d_in[11], (const float*)d_in[12],
        (const float*)d_in[13], (const float*)d_in[14],
        (const float*)d_in[15], (const float*)d_in[16],
        (const float*)d_in[17]);

    kB<<<dim3(BATCH / 128, 4), 256>>>((const float*)d_in[18], (const float*)d_in[19]);

    kC<<<BATCH / 128, 256>>>((const float*)d_in[20], (const float*)d_in[21],
                             (const float*)d_in[22], (const float*)d_in[23],
                             (const float*)d_in[24], (const float*)d_in[25],
                             (const float*)d_in[26], (const float*)d_in[27],
                             (float*)d_out);
}